// round 1
// baseline (speedup 1.0000x reference)
#include <cuda_runtime.h>
#include <math.h>
#include <stdint.h>

#define SEQ 2048
#define DM 1024
#define NH 16
#define NKV 4
#define HDIM 64
#define NE 8
#define NI 3584
#define QKVN 1536
#define NSLOTS (2*SEQ)

// ---------------- scratch (device globals; no allocations) ----------------
__device__ float g_hn[SEQ*DM];
__device__ float g_qkv[SEQ*QKVN];
__device__ float g_q[NH*SEQ*HDIM];
__device__ float g_k[NKV*SEQ*HDIM];
__device__ float g_v[NKV*SEQ*HDIM];
__device__ float g_y[SEQ*DM];
__device__ float g_h[SEQ*DM];
__device__ float g_hf[SEQ*DM];
__device__ int   g_cnt[NE];
__device__ int   g_slot[NE*SEQ];
__device__ float g_wslot[NSLOTS];
__device__ float g_g1[(size_t)NSLOTS*NI];
__device__ float g_g3[(size_t)NSLOTS*NI];
__device__ float g_os[(size_t)NSLOTS*DM];

// ---------------- rmsnorm: one block per row, 256 threads (float4) --------
__global__ __launch_bounds__(256) void rmsnorm_kernel(
    const float* __restrict__ x, const float* __restrict__ w, float* __restrict__ o)
{
    int row = blockIdx.x;
    int tid = threadIdx.x;
    const float4* xr = (const float4*)(x + (size_t)row*DM);
    float4 v = xr[tid];
    float ss = v.x*v.x + v.y*v.y + v.z*v.z + v.w*v.w;
    __shared__ float red[8];
    #pragma unroll
    for (int ofs = 16; ofs > 0; ofs >>= 1) ss += __shfl_down_sync(0xffffffffu, ss, ofs);
    if ((tid & 31) == 0) red[tid >> 5] = ss;
    __syncthreads();
    __shared__ float sr;
    if (tid == 0) {
        float t = 0.f;
        #pragma unroll
        for (int i = 0; i < 8; i++) t += red[i];
        sr = rsqrtf(t / (float)DM + 1e-5f);
    }
    __syncthreads();
    float r = sr;
    const float4* wr = (const float4*)w;
    float4 wv = wr[tid];
    float4 out;
    out.x = v.x*r*wv.x; out.y = v.y*r*wv.y; out.z = v.z*r*wv.z; out.w = v.w*r*wv.w;
    ((float4*)(o + (size_t)row*DM))[tid] = out;
}

// ---------------- SGEMM NT: C[M,N] = A[M,K] * B[N,K]^T (+resid) -----------
// 128x128 tile, BK=8, 256 threads, 8x8 per thread.
__global__ __launch_bounds__(256) void sgemm_nt_kernel(
    const float* __restrict__ A, const float* __restrict__ B,
    const float* __restrict__ resid, float* __restrict__ C,
    int M, int N, int K)
{
    __shared__ float As[8][128];
    __shared__ float Bs[8][128];
    int tid = threadIdx.x;
    int tx = tid & 15, ty = tid >> 4;
    int m0 = blockIdx.y * 128, n0 = blockIdx.x * 128;
    int lrow = tid >> 1;
    int lk   = (tid & 1) * 4;

    float acc[8][8];
    #pragma unroll
    for (int i = 0; i < 8; i++)
        #pragma unroll
        for (int j = 0; j < 8; j++) acc[i][j] = 0.f;

    const float* Arow = A + (size_t)(m0 + lrow) * K;
    const float* Brow = B + (size_t)(n0 + lrow) * K;
    bool avalid = (m0 + lrow) < M;

    for (int k0 = 0; k0 < K; k0 += 8) {
        float4 a4 = avalid ? *(const float4*)(Arow + k0 + lk) : make_float4(0.f,0.f,0.f,0.f);
        float4 b4 = *(const float4*)(Brow + k0 + lk);
        As[lk+0][lrow] = a4.x; As[lk+1][lrow] = a4.y; As[lk+2][lrow] = a4.z; As[lk+3][lrow] = a4.w;
        Bs[lk+0][lrow] = b4.x; Bs[lk+1][lrow] = b4.y; Bs[lk+2][lrow] = b4.z; Bs[lk+3][lrow] = b4.w;
        __syncthreads();
        #pragma unroll
        for (int kk = 0; kk < 8; kk++) {
            float a[8], b[8];
            *(float4*)&a[0] = *(const float4*)&As[kk][ty*8];
            *(float4*)&a[4] = *(const float4*)&As[kk][ty*8+4];
            *(float4*)&b[0] = *(const float4*)&Bs[kk][tx*8];
            *(float4*)&b[4] = *(const float4*)&Bs[kk][tx*8+4];
            #pragma unroll
            for (int i = 0; i < 8; i++)
                #pragma unroll
                for (int j = 0; j < 8; j++) acc[i][j] += a[i] * b[j];
        }
        __syncthreads();
    }

    #pragma unroll
    for (int i = 0; i < 8; i++) {
        int gm = m0 + ty*8 + i;
        if (gm >= M) continue;
        float* crow = C + (size_t)gm*N + n0 + tx*8;
        #pragma unroll
        for (int j = 0; j < 8; j += 4) {
            float4 v;
            v.x = acc[i][j+0]; v.y = acc[i][j+1]; v.z = acc[i][j+2]; v.w = acc[i][j+3];
            if (resid) {
                const float4 rv = *(const float4*)(resid + (size_t)gm*N + n0 + tx*8 + j);
                v.x += rv.x; v.y += rv.y; v.z += rv.z; v.w += rv.w;
            }
            *(float4*)(crow + j) = v;
        }
    }
}

// ---------------- gathered SGEMM for MoE (per-expert via blockIdx.z) ------
// A row index = slot >> shiftA (shiftA=1: token rows of hf; 0: slot rows of g)
// C row index = slot. B is per-expert weight [N,K].
__global__ __launch_bounds__(256) void sgemm_gather_kernel(
    const float* __restrict__ A, const float* __restrict__ B,
    float* __restrict__ C, int N, int K, int shiftA)
{
    int e = blockIdx.z;
    int cnt = g_cnt[e];
    int m0 = blockIdx.y * 128;
    if (m0 >= cnt) return;
    const int* sl = g_slot + e * SEQ;
    const float* Be = B + (size_t)e * N * K;

    __shared__ float As[8][128];
    __shared__ float Bs[8][128];
    int tid = threadIdx.x;
    int tx = tid & 15, ty = tid >> 4;
    int n0 = blockIdx.x * 128;
    int lrow = tid >> 1;
    int lk   = (tid & 1) * 4;

    float acc[8][8];
    #pragma unroll
    for (int i = 0; i < 8; i++)
        #pragma unroll
        for (int j = 0; j < 8; j++) acc[i][j] = 0.f;

    int gm = m0 + lrow;
    const float* Arow = nullptr;
    if (gm < cnt) {
        int slot = sl[gm];
        Arow = A + (size_t)(slot >> shiftA) * K;
    }
    const float* Brow = Be + (size_t)(n0 + lrow) * K;

    for (int k0 = 0; k0 < K; k0 += 8) {
        float4 a4 = Arow ? *(const float4*)(Arow + k0 + lk) : make_float4(0.f,0.f,0.f,0.f);
        float4 b4 = *(const float4*)(Brow + k0 + lk);
        As[lk+0][lrow] = a4.x; As[lk+1][lrow] = a4.y; As[lk+2][lrow] = a4.z; As[lk+3][lrow] = a4.w;
        Bs[lk+0][lrow] = b4.x; Bs[lk+1][lrow] = b4.y; Bs[lk+2][lrow] = b4.z; Bs[lk+3][lrow] = b4.w;
        __syncthreads();
        #pragma unroll
        for (int kk = 0; kk < 8; kk++) {
            float a[8], b[8];
            *(float4*)&a[0] = *(const float4*)&As[kk][ty*8];
            *(float4*)&a[4] = *(const float4*)&As[kk][ty*8+4];
            *(float4*)&b[0] = *(const float4*)&Bs[kk][tx*8];
            *(float4*)&b[4] = *(const float4*)&Bs[kk][tx*8+4];
            #pragma unroll
            for (int i = 0; i < 8; i++)
                #pragma unroll
                for (int j = 0; j < 8; j++) acc[i][j] += a[i] * b[j];
        }
        __syncthreads();
    }

    #pragma unroll
    for (int i = 0; i < 8; i++) {
        int gmi = m0 + ty*8 + i;
        if (gmi >= cnt) continue;
        int slot = sl[gmi];
        float* crow = C + (size_t)slot*N + n0 + tx*8;
        #pragma unroll
        for (int j = 0; j < 8; j += 4) {
            float4 v;
            v.x = acc[i][j+0]; v.y = acc[i][j+1]; v.z = acc[i][j+2]; v.w = acc[i][j+3];
            *(float4*)(crow + j) = v;
        }
    }
}

// ---------------- RoPE + QKV split ----------------------------------------
// qkv [S,1536] -> q [H,S,64] (rope), k [KVH,S,64] (rope), v [KVH,S,64]
__global__ void rope_split_kernel(const float* __restrict__ freqs)
{
    int idx = blockIdx.x * blockDim.x + threadIdx.x;
    if (idx >= SEQ * (QKVN/2)) return;
    int t = idx / (QKVN/2);
    int col = (idx % (QKVN/2)) * 2;
    float x0 = g_qkv[(size_t)t*QKVN + col];
    float x1 = g_qkv[(size_t)t*QKVN + col + 1];
    if (col < DM) {
        int h = col >> 6, d = col & 63, p = d >> 1;
        float cs = freqs[((size_t)t*32 + p)*2 + 0];
        float sn = freqs[((size_t)t*32 + p)*2 + 1];
        float o0 = x0*cs - x1*sn;
        float o1 = x1*cs + x0*sn;
        size_t base = ((size_t)h*SEQ + t)*HDIM + d;
        g_q[base] = o0; g_q[base+1] = o1;
    } else if (col < DM + NKV*HDIM) {
        int c = col - DM;
        int kh = c >> 6, d = c & 63, p = d >> 1;
        float cs = freqs[((size_t)t*32 + p)*2 + 0];
        float sn = freqs[((size_t)t*32 + p)*2 + 1];
        float o0 = x0*cs - x1*sn;
        float o1 = x1*cs + x0*sn;
        size_t base = ((size_t)kh*SEQ + t)*HDIM + d;
        g_k[base] = o0; g_k[base+1] = o1;
    } else {
        int c = col - DM - NKV*HDIM;
        int vh = c >> 6, d = c & 63;
        size_t base = ((size_t)vh*SEQ + t)*HDIM + d;
        g_v[base] = x0; g_v[base+1] = x1;
    }
}

// ---------------- flash attention (causal, GQA) ----------------------------
// grid (32 qtiles, 16 heads), block = 64 threads (one query row each)
#define KSTR 68
#define SSTR 65
__global__ __launch_bounds__(64) void attn_kernel()
{
    extern __shared__ float sm[];
    float* Ks = sm;
    float* Vs = sm + 64*KSTR;
    float* Ss = sm + 2*64*KSTR;

    int qt = blockIdx.x, h = blockIdx.y;
    int tid = threadIdx.x;
    int qi = qt*64 + tid;
    int kvh = h >> 2;

    const float4* qr = (const float4*)(g_q + ((size_t)h*SEQ + qi)*HDIM);
    float4 q4[16];
    #pragma unroll
    for (int i = 0; i < 16; i++) {
        float4 v = qr[i];
        q4[i].x = v.x*0.125f; q4[i].y = v.y*0.125f; q4[i].z = v.z*0.125f; q4[i].w = v.w*0.125f;
    }
    float4 o4[16];
    #pragma unroll
    for (int i = 0; i < 16; i++) o4[i] = make_float4(0.f,0.f,0.f,0.f);
    float m = -INFINITY, l = 0.f;

    for (int kt = 0; kt <= qt; kt++) {
        const float4* kb = (const float4*)(g_k + ((size_t)kvh*SEQ + kt*64)*HDIM);
        const float4* vb = (const float4*)(g_v + ((size_t)kvh*SEQ + kt*64)*HDIM);
        for (int i = tid; i < 1024; i += 64) {
            int r = i >> 4, c = i & 15;
            *(float4*)&Ks[r*KSTR + c*4] = kb[i];
            *(float4*)&Vs[r*KSTR + c*4] = vb[i];
        }
        __syncthreads();

        float tm = -INFINITY;
        for (int j = 0; j < 64; j++) {
            int kj = (kt << 6) + j;
            float s = -INFINITY;
            if (kj <= qi) {
                s = 0.f;
                const float4* kr = (const float4*)&Ks[j*KSTR];
                #pragma unroll
                for (int i = 0; i < 16; i++) {
                    float4 kv = kr[i];
                    s += q4[i].x*kv.x + q4[i].y*kv.y + q4[i].z*kv.z + q4[i].w*kv.w;
                }
            }
            Ss[tid*SSTR + j] = s;
            tm = fmaxf(tm, s);
        }
        float mn = fmaxf(m, tm);
        float sc = expf(m - mn);
        l *= sc;
        #pragma unroll
        for (int i = 0; i < 16; i++) {
            o4[i].x *= sc; o4[i].y *= sc; o4[i].z *= sc; o4[i].w *= sc;
        }
        for (int j = 0; j < 64; j++) {
            float p = expf(Ss[tid*SSTR + j] - mn);
            l += p;
            const float4* vr = (const float4*)&Vs[j*KSTR];
            #pragma unroll
            for (int i = 0; i < 16; i++) {
                float4 vv = vr[i];
                o4[i].x += p*vv.x; o4[i].y += p*vv.y; o4[i].z += p*vv.z; o4[i].w += p*vv.w;
            }
        }
        m = mn;
        __syncthreads();
    }

    float inv = 1.f / l;
    float4* yr = (float4*)(g_y + (size_t)qi*DM + h*HDIM);
    #pragma unroll
    for (int i = 0; i < 16; i++) {
        float4 v;
        v.x = o4[i].x*inv; v.y = o4[i].y*inv; v.z = o4[i].z*inv; v.w = o4[i].w*inv;
        yr[i] = v;
    }
}

// ---------------- gating: softmax over 8 experts, top-2 -------------------
__global__ __launch_bounds__(256) void gating_kernel(const float* __restrict__ gw)
{
    int t = blockIdx.x;
    int tid = threadIdx.x;
    int e = tid >> 5, lane = tid & 31;
    float s = 0.f;
    const float* hr = g_hf + (size_t)t*DM;
    const float* wr = gw + (size_t)e*DM;
    for (int d = lane; d < DM; d += 32) s += hr[d]*wr[d];
    #pragma unroll
    for (int ofs = 16; ofs > 0; ofs >>= 1) s += __shfl_down_sync(0xffffffffu, s, ofs);
    __shared__ float lg[NE];
    if (lane == 0) lg[e] = s;
    __syncthreads();
    if (tid == 0) {
        float mx = lg[0];
        #pragma unroll
        for (int i = 1; i < NE; i++) mx = fmaxf(mx, lg[i]);
        float p[NE]; float den = 0.f;
        #pragma unroll
        for (int i = 0; i < NE; i++) { p[i] = expf(lg[i]-mx); den += p[i]; }
        #pragma unroll
        for (int i = 0; i < NE; i++) p[i] /= den;
        int i1 = 0;
        #pragma unroll
        for (int i = 1; i < NE; i++) if (p[i] > p[i1]) i1 = i;
        int i2 = (i1 == 0) ? 1 : 0;
        #pragma unroll
        for (int i = 0; i < NE; i++) if (i != i1 && p[i] > p[i2]) i2 = i;
        float w1 = p[i1], w2 = p[i2];
        float sw = w1 + w2;
        w1 /= sw; w2 /= sw;
        int pos1 = atomicAdd(&g_cnt[i1], 1);
        g_slot[i1*SEQ + pos1] = 2*t;
        g_wslot[2*t] = w1;
        int pos2 = atomicAdd(&g_cnt[i2], 1);
        g_slot[i2*SEQ + pos2] = 2*t + 1;
        g_wslot[2*t+1] = w2;
    }
}

// ---------------- silu(g1)*g3 -> g1 ----------------------------------------
__global__ void silu_mul_kernel()
{
    size_t i = (size_t)blockIdx.x * blockDim.x + threadIdx.x;
    size_t n4 = (size_t)NSLOTS * NI / 4;
    if (i >= n4) return;
    float4 a = ((const float4*)g_g1)[i];
    float4 b = ((const float4*)g_g3)[i];
    float4 o;
    o.x = (a.x / (1.f + expf(-a.x))) * b.x;
    o.y = (a.y / (1.f + expf(-a.y))) * b.y;
    o.z = (a.z / (1.f + expf(-a.z))) * b.z;
    o.w = (a.w / (1.f + expf(-a.w))) * b.w;
    ((float4*)g_g1)[i] = o;
}

// ---------------- final combine: out = h + w0*os[2t] + w1*os[2t+1] --------
__global__ __launch_bounds__(256) void combine_kernel(float* __restrict__ out)
{
    int t = blockIdx.x;
    int tid = threadIdx.x;
    float w0 = g_wslot[2*t], w1 = g_wslot[2*t+1];
    float4 hv = ((const float4*)(g_h + (size_t)t*DM))[tid];
    float4 a = ((const float4*)(g_os + (size_t)(2*t)*DM))[tid];
    float4 b = ((const float4*)(g_os + (size_t)(2*t+1)*DM))[tid];
    float4 o;
    o.x = hv.x + w0*a.x + w1*b.x;
    o.y = hv.y + w0*a.y + w1*b.y;
    o.z = hv.z + w0*a.z + w1*b.z;
    o.w = hv.w + w0*a.w + w1*b.w;
    ((float4*)(out + (size_t)t*DM))[tid] = o;
}

// ---------------- host launch ----------------------------------------------
extern "C" void kernel_launch(void* const* d_in, const int* in_sizes, int n_in,
                              void* d_out, int out_size)
{
    const float* x      = (const float*)d_in[0];
    const float* wqkv   = (const float*)d_in[1];
    const float* wo     = (const float*)d_in[2];
    const float* gate_w = (const float*)d_in[3];
    const float* w1     = (const float*)d_in[4];
    const float* w2     = (const float*)d_in[5];
    const float* w3     = (const float*)d_in[6];
    const float* anw    = (const float*)d_in[7];
    const float* fnw    = (const float*)d_in[8];
    const float* freqs  = (const float*)d_in[9];
    float* out = (float*)d_out;

    float *p_hn, *p_qkv, *p_y, *p_h, *p_hf, *p_g1, *p_g3, *p_os;
    int *p_cnt;
    cudaGetSymbolAddress((void**)&p_hn,  g_hn);
    cudaGetSymbolAddress((void**)&p_qkv, g_qkv);
    cudaGetSymbolAddress((void**)&p_y,   g_y);
    cudaGetSymbolAddress((void**)&p_h,   g_h);
    cudaGetSymbolAddress((void**)&p_hf,  g_hf);
    cudaGetSymbolAddress((void**)&p_g1,  g_g1);
    cudaGetSymbolAddress((void**)&p_g3,  g_g3);
    cudaGetSymbolAddress((void**)&p_os,  g_os);
    cudaGetSymbolAddress((void**)&p_cnt, g_cnt);

    static bool attr_set = false;
    if (!attr_set) {
        cudaFuncSetAttribute(attn_kernel, cudaFuncAttributeMaxDynamicSharedMemorySize,
                             (2*64*KSTR + 64*SSTR) * (int)sizeof(float));
        attr_set = true;
    }

    // 1. attn rmsnorm
    rmsnorm_kernel<<<SEQ, 256>>>(x, anw, p_hn);
    // 2. qkv = hn @ wqkv^T
    sgemm_nt_kernel<<<dim3(QKVN/128, SEQ/128), 256>>>(p_hn, wqkv, nullptr, p_qkv, SEQ, QKVN, DM);
    // 3. rope + split
    {
        int total = SEQ * (QKVN/2);
        rope_split_kernel<<<(total + 255)/256, 256>>>(freqs);
    }
    // 4. attention
    attn_kernel<<<dim3(SEQ/64, NH), 64, (2*64*KSTR + 64*SSTR)*(int)sizeof(float)>>>();
    // 5. h = x + y @ wo^T
    sgemm_nt_kernel<<<dim3(DM/128, SEQ/128), 256>>>(p_y, wo, x, p_h, SEQ, DM, DM);
    // 6. ffn rmsnorm
    rmsnorm_kernel<<<SEQ, 256>>>(p_h, fnw, p_hf);
    // 7. gating
    cudaMemsetAsync(p_cnt, 0, NE*sizeof(int), 0);
    gating_kernel<<<SEQ, 256>>>(gate_w);
    // 8. MoE expert GEMMs (gathered, only selected experts)
    sgemm_gather_kernel<<<dim3(NI/128, SEQ/128, NE), 256>>>(p_hf, w1, p_g1, NI, DM, 1);
    sgemm_gather_kernel<<<dim3(NI/128, SEQ/128, NE), 256>>>(p_hf, w3, p_g3, NI, DM, 1);
    // 9. g = silu(g1) * g3
    {
        size_t n4 = (size_t)NSLOTS * NI / 4;
        silu_mul_kernel<<<(int)((n4 + 255)/256), 256>>>();
    }
    // 10. out_slot = g @ w2^T
    sgemm_gather_kernel<<<dim3(DM/128, SEQ/128, NE), 256>>>(p_g1, w2, p_os, DM, NI, 0);
    // 11. combine
    combine_kernel<<<SEQ, 256>>>(out);
}

// round 2
// speedup vs baseline: 1.5863x; 1.5863x over previous
#include <cuda_runtime.h>
#include <math.h>
#include <stdint.h>

#define SEQ 2048
#define DM 1024
#define NH 16
#define NKV 4
#define HDIM 64
#define NE 8
#define NI 3584
#define QKVN 1536
#define NSLOTS (2*SEQ)

// ---------------- scratch (device globals; no allocations) ----------------
__device__ float g_hn[SEQ*DM];
__device__ float g_qkv[SEQ*QKVN];
__device__ float g_q[NH*SEQ*HDIM];
__device__ float g_k[NKV*SEQ*HDIM];
__device__ float g_v[NKV*SEQ*HDIM];
__device__ float g_y[SEQ*DM];
__device__ float g_h[SEQ*DM];
__device__ float g_hf[SEQ*DM];
__device__ int   g_cnt[NE];
__device__ int   g_slot[NE*SEQ];
__device__ float g_wslot[NSLOTS];
__device__ float g_g1[(size_t)NSLOTS*NI];
__device__ float g_g3[(size_t)NSLOTS*NI];
__device__ float g_os[(size_t)NSLOTS*DM];

// ---------------- helpers ---------------------------------------------------
__device__ __forceinline__ uint32_t f2tf32(float f) {
    uint32_t r;
    asm("cvt.rna.tf32.f32 %0, %1;" : "=r"(r) : "f"(f));
    return r;
}

__device__ __forceinline__ void mma_tf32(float c[4],
    uint32_t a0, uint32_t a1, uint32_t a2, uint32_t a3,
    uint32_t b0, uint32_t b1)
{
    asm volatile(
        "mma.sync.aligned.m16n8k8.row.col.f32.tf32.tf32.f32 "
        "{%0,%1,%2,%3}, {%4,%5,%6,%7}, {%8,%9}, {%0,%1,%2,%3};"
        : "+f"(c[0]), "+f"(c[1]), "+f"(c[2]), "+f"(c[3])
        : "r"(a0), "r"(a1), "r"(a2), "r"(a3), "r"(b0), "r"(b1));
}

// ---------------- rmsnorm: one block per row, 256 threads (float4) --------
__global__ __launch_bounds__(256) void rmsnorm_kernel(
    const float* __restrict__ x, const float* __restrict__ w, float* __restrict__ o)
{
    int row = blockIdx.x;
    int tid = threadIdx.x;
    const float4* xr = (const float4*)(x + (size_t)row*DM);
    float4 v = xr[tid];
    float ss = v.x*v.x + v.y*v.y + v.z*v.z + v.w*v.w;
    __shared__ float red[8];
    #pragma unroll
    for (int ofs = 16; ofs > 0; ofs >>= 1) ss += __shfl_down_sync(0xffffffffu, ss, ofs);
    if ((tid & 31) == 0) red[tid >> 5] = ss;
    __syncthreads();
    __shared__ float sr;
    if (tid == 0) {
        float t = 0.f;
        #pragma unroll
        for (int i = 0; i < 8; i++) t += red[i];
        sr = rsqrtf(t / (float)DM + 1e-5f);
    }
    __syncthreads();
    float r = sr;
    const float4* wr = (const float4*)w;
    float4 wv = wr[tid];
    float4 out;
    out.x = v.x*r*wv.x; out.y = v.y*r*wv.y; out.z = v.z*r*wv.z; out.w = v.w*r*wv.w;
    ((float4*)(o + (size_t)row*DM))[tid] = out;
}

// ---------------- TF32 tensor-core GEMM NT ---------------------------------
// C[M,N] = A[M,K] * B[N,K]^T  (+ optional resid).
// 128x128 tile, BK=16, 256 threads = 8 warps (2x4), warp tile 64x32,
// mma.sync m16n8k8 tf32, double-buffered smem with 136-word row stride
// (conflict-free fragment loads: bank = tig*8+groupID covers 0..31).
// GATHER variant: per-expert via blockIdx.z, A rows via slot list,
// C rows scattered by slot id.
template<bool GATHER>
__global__ __launch_bounds__(256) void gemm_tf32_kernel(
    const float* __restrict__ A, const float* __restrict__ B,
    const float* __restrict__ resid, float* __restrict__ C,
    int M, int N, int K, int shiftA)
{
    __shared__ uint32_t As[2][16][136];
    __shared__ uint32_t Bs[2][16][136];

    const int* sl = nullptr;
    if (GATHER) {
        int e = blockIdx.z;
        M = g_cnt[e];
        if ((int)blockIdx.y * 128 >= M) return;
        sl = g_slot + e * SEQ;
        B += (size_t)e * N * K;
    }
    int m0 = blockIdx.y * 128, n0 = blockIdx.x * 128;
    int tid = threadIdx.x;
    int warp = tid >> 5, lane = tid & 31;
    int wm = (warp >> 2) * 64, wn = (warp & 3) * 32;
    int g = lane >> 2, tg = lane & 3;

    // global-load assignment: thread -> (row lr in tile, k offset lk in {0,8})
    int lr = tid & 127;
    int lk = (tid >> 7) * 8;

    bool aval;
    const float* Arow;
    if (GATHER) {
        int gm = m0 + lr;
        aval = gm < M;
        Arow = aval ? (A + (size_t)(sl[gm] >> shiftA) * K) : A;
    } else {
        aval = true;
        Arow = A + (size_t)(m0 + lr) * K;
    }
    const float* Brow = B + (size_t)(n0 + lr) * K;

    float acc[4][4][4];
    #pragma unroll
    for (int i = 0; i < 4; i++)
        #pragma unroll
        for (int j = 0; j < 4; j++)
            #pragma unroll
            for (int q = 0; q < 4; q++) acc[i][j][q] = 0.f;

    uint32_t ra[8], rb[8];

    // prefetch tile 0
    {
        float4 a1 = aval ? *(const float4*)(Arow + lk)     : make_float4(0,0,0,0);
        float4 a2 = aval ? *(const float4*)(Arow + lk + 4) : make_float4(0,0,0,0);
        float4 b1 = *(const float4*)(Brow + lk);
        float4 b2 = *(const float4*)(Brow + lk + 4);
        ra[0]=f2tf32(a1.x); ra[1]=f2tf32(a1.y); ra[2]=f2tf32(a1.z); ra[3]=f2tf32(a1.w);
        ra[4]=f2tf32(a2.x); ra[5]=f2tf32(a2.y); ra[6]=f2tf32(a2.z); ra[7]=f2tf32(a2.w);
        rb[0]=f2tf32(b1.x); rb[1]=f2tf32(b1.y); rb[2]=f2tf32(b1.z); rb[3]=f2tf32(b1.w);
        rb[4]=f2tf32(b2.x); rb[5]=f2tf32(b2.y); rb[6]=f2tf32(b2.z); rb[7]=f2tf32(b2.w);
        #pragma unroll
        for (int j = 0; j < 8; j++) { As[0][lk+j][lr] = ra[j]; Bs[0][lk+j][lr] = rb[j]; }
    }
    __syncthreads();

    int cur = 0;
    for (int k0 = 16; ; k0 += 16) {
        bool more = k0 < K;
        if (more) {
            float4 a1 = aval ? *(const float4*)(Arow + k0 + lk)     : make_float4(0,0,0,0);
            float4 a2 = aval ? *(const float4*)(Arow + k0 + lk + 4) : make_float4(0,0,0,0);
            float4 b1 = *(const float4*)(Brow + k0 + lk);
            float4 b2 = *(const float4*)(Brow + k0 + lk + 4);
            ra[0]=f2tf32(a1.x); ra[1]=f2tf32(a1.y); ra[2]=f2tf32(a1.z); ra[3]=f2tf32(a1.w);
            ra[4]=f2tf32(a2.x); ra[5]=f2tf32(a2.y); ra[6]=f2tf32(a2.z); ra[7]=f2tf32(a2.w);
            rb[0]=f2tf32(b1.x); rb[1]=f2tf32(b1.y); rb[2]=f2tf32(b1.z); rb[3]=f2tf32(b1.w);
            rb[4]=f2tf32(b2.x); rb[5]=f2tf32(b2.y); rb[6]=f2tf32(b2.z); rb[7]=f2tf32(b2.w);
        }
        #pragma unroll
        for (int kk = 0; kk < 16; kk += 8) {
            uint32_t af[4][4], bf[4][2];
            #pragma unroll
            for (int i = 0; i < 4; i++) {
                int mb = wm + i*16 + g;
                af[i][0] = As[cur][kk+tg  ][mb];
                af[i][1] = As[cur][kk+tg  ][mb+8];
                af[i][2] = As[cur][kk+tg+4][mb];
                af[i][3] = As[cur][kk+tg+4][mb+8];
            }
            #pragma unroll
            for (int j = 0; j < 4; j++) {
                int nb = wn + j*8 + g;
                bf[j][0] = Bs[cur][kk+tg  ][nb];
                bf[j][1] = Bs[cur][kk+tg+4][nb];
            }
            #pragma unroll
            for (int i = 0; i < 4; i++)
                #pragma unroll
                for (int j = 0; j < 4; j++)
                    mma_tf32(acc[i][j], af[i][0], af[i][1], af[i][2], af[i][3],
                             bf[j][0], bf[j][1]);
        }
        if (!more) break;
        #pragma unroll
        for (int j = 0; j < 8; j++) { As[cur^1][lk+j][lr] = ra[j]; Bs[cur^1][lk+j][lr] = rb[j]; }
        __syncthreads();
        cur ^= 1;
    }

    // epilogue
    #pragma unroll
    for (int i = 0; i < 4; i++) {
        int r0 = m0 + wm + i*16 + g;
        int r1 = r0 + 8;
        bool v0, v1;
        int row0, row1;
        if (GATHER) {
            v0 = r0 < M; v1 = r1 < M;
            row0 = v0 ? sl[r0] : 0;
            row1 = v1 ? sl[r1] : 0;
        } else {
            v0 = v1 = true; row0 = r0; row1 = r1;
        }
        #pragma unroll
        for (int j = 0; j < 4; j++) {
            int c0 = n0 + wn + j*8 + tg*2;
            if (v0) {
                float2 v; v.x = acc[i][j][0]; v.y = acc[i][j][1];
                if (resid) {
                    v.x += resid[(size_t)row0*N + c0];
                    v.y += resid[(size_t)row0*N + c0 + 1];
                }
                *(float2*)(C + (size_t)row0*N + c0) = v;
            }
            if (v1) {
                float2 v; v.x = acc[i][j][2]; v.y = acc[i][j][3];
                if (resid) {
                    v.x += resid[(size_t)row1*N + c0];
                    v.y += resid[(size_t)row1*N + c0 + 1];
                }
                *(float2*)(C + (size_t)row1*N + c0) = v;
            }
        }
    }
}

// ---------------- RoPE + QKV split ----------------------------------------
__global__ void rope_split_kernel(const float* __restrict__ freqs)
{
    int idx = blockIdx.x * blockDim.x + threadIdx.x;
    if (idx >= SEQ * (QKVN/2)) return;
    int t = idx / (QKVN/2);
    int col = (idx % (QKVN/2)) * 2;
    float x0 = g_qkv[(size_t)t*QKVN + col];
    float x1 = g_qkv[(size_t)t*QKVN + col + 1];
    if (col < DM) {
        int h = col >> 6, d = col & 63, p = d >> 1;
        float cs = freqs[((size_t)t*32 + p)*2 + 0];
        float sn = freqs[((size_t)t*32 + p)*2 + 1];
        float o0 = x0*cs - x1*sn;
        float o1 = x1*cs + x0*sn;
        size_t base = ((size_t)h*SEQ + t)*HDIM + d;
        g_q[base] = o0; g_q[base+1] = o1;
    } else if (col < DM + NKV*HDIM) {
        int c = col - DM;
        int kh = c >> 6, d = c & 63, p = d >> 1;
        float cs = freqs[((size_t)t*32 + p)*2 + 0];
        float sn = freqs[((size_t)t*32 + p)*2 + 1];
        float o0 = x0*cs - x1*sn;
        float o1 = x1*cs + x0*sn;
        size_t base = ((size_t)kh*SEQ + t)*HDIM + d;
        g_k[base] = o0; g_k[base+1] = o1;
    } else {
        int c = col - DM - NKV*HDIM;
        int vh = c >> 6, d = c & 63;
        size_t base = ((size_t)vh*SEQ + t)*HDIM + d;
        g_v[base] = x0; g_v[base+1] = x1;
    }
}

// ---------------- flash attention (causal, GQA) ----------------------------
#define KSTR 68
#define SSTR 65
__global__ __launch_bounds__(64) void attn_kernel()
{
    extern __shared__ float sm[];
    float* Ks = sm;
    float* Vs = sm + 64*KSTR;
    float* Ss = sm + 2*64*KSTR;

    int qt = blockIdx.x, h = blockIdx.y;
    int tid = threadIdx.x;
    int qi = qt*64 + tid;
    int kvh = h >> 2;

    const float4* qr = (const float4*)(g_q + ((size_t)h*SEQ + qi)*HDIM);
    float4 q4[16];
    #pragma unroll
    for (int i = 0; i < 16; i++) {
        float4 v = qr[i];
        q4[i].x = v.x*0.125f; q4[i].y = v.y*0.125f; q4[i].z = v.z*0.125f; q4[i].w = v.w*0.125f;
    }
    float4 o4[16];
    #pragma unroll
    for (int i = 0; i < 16; i++) o4[i] = make_float4(0.f,0.f,0.f,0.f);
    float m = -INFINITY, l = 0.f;

    for (int kt = 0; kt <= qt; kt++) {
        const float4* kb = (const float4*)(g_k + ((size_t)kvh*SEQ + kt*64)*HDIM);
        const float4* vb = (const float4*)(g_v + ((size_t)kvh*SEQ + kt*64)*HDIM);
        for (int i = tid; i < 1024; i += 64) {
            int r = i >> 4, c = i & 15;
            *(float4*)&Ks[r*KSTR + c*4] = kb[i];
            *(float4*)&Vs[r*KSTR + c*4] = vb[i];
        }
        __syncthreads();

        float tm = -INFINITY;
        for (int j = 0; j < 64; j++) {
            int kj = (kt << 6) + j;
            float s = -INFINITY;
            if (kj <= qi) {
                s = 0.f;
                const float4* kr = (const float4*)&Ks[j*KSTR];
                #pragma unroll
                for (int i = 0; i < 16; i++) {
                    float4 kv = kr[i];
                    s += q4[i].x*kv.x + q4[i].y*kv.y + q4[i].z*kv.z + q4[i].w*kv.w;
                }
            }
            Ss[tid*SSTR + j] = s;
            tm = fmaxf(tm, s);
        }
        float mn = fmaxf(m, tm);
        float sc = expf(m - mn);
        l *= sc;
        #pragma unroll
        for (int i = 0; i < 16; i++) {
            o4[i].x *= sc; o4[i].y *= sc; o4[i].z *= sc; o4[i].w *= sc;
        }
        for (int j = 0; j < 64; j++) {
            float p = expf(Ss[tid*SSTR + j] - mn);
            l += p;
            const float4* vr = (const float4*)&Vs[j*KSTR];
            #pragma unroll
            for (int i = 0; i < 16; i++) {
                float4 vv = vr[i];
                o4[i].x += p*vv.x; o4[i].y += p*vv.y; o4[i].z += p*vv.z; o4[i].w += p*vv.w;
            }
        }
        m = mn;
        __syncthreads();
    }

    float inv = 1.f / l;
    float4* yr = (float4*)(g_y + (size_t)qi*DM + h*HDIM);
    #pragma unroll
    for (int i = 0; i < 16; i++) {
        float4 v;
        v.x = o4[i].x*inv; v.y = o4[i].y*inv; v.z = o4[i].z*inv; v.w = o4[i].w*inv;
        yr[i] = v;
    }
}

// ---------------- gating: softmax over 8 experts, top-2 -------------------
__global__ __launch_bounds__(256) void gating_kernel(const float* __restrict__ gw)
{
    int t = blockIdx.x;
    int tid = threadIdx.x;
    int e = tid >> 5, lane = tid & 31;
    float s = 0.f;
    const float* hr = g_hf + (size_t)t*DM;
    const float* wr = gw + (size_t)e*DM;
    for (int d = lane; d < DM; d += 32) s += hr[d]*wr[d];
    #pragma unroll
    for (int ofs = 16; ofs > 0; ofs >>= 1) s += __shfl_down_sync(0xffffffffu, s, ofs);
    __shared__ float lg[NE];
    if (lane == 0) lg[e] = s;
    __syncthreads();
    if (tid == 0) {
        float mx = lg[0];
        #pragma unroll
        for (int i = 1; i < NE; i++) mx = fmaxf(mx, lg[i]);
        float p[NE]; float den = 0.f;
        #pragma unroll
        for (int i = 0; i < NE; i++) { p[i] = expf(lg[i]-mx); den += p[i]; }
        #pragma unroll
        for (int i = 0; i < NE; i++) p[i] /= den;
        int i1 = 0;
        #pragma unroll
        for (int i = 1; i < NE; i++) if (p[i] > p[i1]) i1 = i;
        int i2 = (i1 == 0) ? 1 : 0;
        #pragma unroll
        for (int i = 0; i < NE; i++) if (i != i1 && p[i] > p[i2]) i2 = i;
        float w1 = p[i1], w2 = p[i2];
        float sw = w1 + w2;
        w1 /= sw; w2 /= sw;
        int pos1 = atomicAdd(&g_cnt[i1], 1);
        g_slot[i1*SEQ + pos1] = 2*t;
        g_wslot[2*t] = w1;
        int pos2 = atomicAdd(&g_cnt[i2], 1);
        g_slot[i2*SEQ + pos2] = 2*t + 1;
        g_wslot[2*t+1] = w2;
    }
}

// ---------------- silu(g1)*g3 -> g1 ----------------------------------------
__global__ void silu_mul_kernel()
{
    size_t i = (size_t)blockIdx.x * blockDim.x + threadIdx.x;
    size_t n4 = (size_t)NSLOTS * NI / 4;
    if (i >= n4) return;
    float4 a = ((const float4*)g_g1)[i];
    float4 b = ((const float4*)g_g3)[i];
    float4 o;
    o.x = (a.x / (1.f + expf(-a.x))) * b.x;
    o.y = (a.y / (1.f + expf(-a.y))) * b.y;
    o.z = (a.z / (1.f + expf(-a.z))) * b.z;
    o.w = (a.w / (1.f + expf(-a.w))) * b.w;
    ((float4*)g_g1)[i] = o;
}

// ---------------- final combine: out = h + w0*os[2t] + w1*os[2t+1] --------
__global__ __launch_bounds__(256) void combine_kernel(float* __restrict__ out)
{
    int t = blockIdx.x;
    int tid = threadIdx.x;
    float w0 = g_wslot[2*t], w1 = g_wslot[2*t+1];
    float4 hv = ((const float4*)(g_h + (size_t)t*DM))[tid];
    float4 a = ((const float4*)(g_os + (size_t)(2*t)*DM))[tid];
    float4 b = ((const float4*)(g_os + (size_t)(2*t+1)*DM))[tid];
    float4 o;
    o.x = hv.x + w0*a.x + w1*b.x;
    o.y = hv.y + w0*a.y + w1*b.y;
    o.z = hv.z + w0*a.z + w1*b.z;
    o.w = hv.w + w0*a.w + w1*b.w;
    ((float4*)(out + (size_t)t*DM))[tid] = o;
}

// ---------------- host launch ----------------------------------------------
extern "C" void kernel_launch(void* const* d_in, const int* in_sizes, int n_in,
                              void* d_out, int out_size)
{
    const float* x      = (const float*)d_in[0];
    const float* wqkv   = (const float*)d_in[1];
    const float* wo     = (const float*)d_in[2];
    const float* gate_w = (const float*)d_in[3];
    const float* w1     = (const float*)d_in[4];
    const float* w2     = (const float*)d_in[5];
    const float* w3     = (const float*)d_in[6];
    const float* anw    = (const float*)d_in[7];
    const float* fnw    = (const float*)d_in[8];
    const float* freqs  = (const float*)d_in[9];
    float* out = (float*)d_out;

    float *p_hn, *p_qkv, *p_y, *p_h, *p_hf, *p_g1, *p_g3, *p_os;
    int *p_cnt;
    cudaGetSymbolAddress((void**)&p_hn,  g_hn);
    cudaGetSymbolAddress((void**)&p_qkv, g_qkv);
    cudaGetSymbolAddress((void**)&p_y,   g_y);
    cudaGetSymbolAddress((void**)&p_h,   g_h);
    cudaGetSymbolAddress((void**)&p_hf,  g_hf);
    cudaGetSymbolAddress((void**)&p_g1,  g_g1);
    cudaGetSymbolAddress((void**)&p_g3,  g_g3);
    cudaGetSymbolAddress((void**)&p_os,  g_os);
    cudaGetSymbolAddress((void**)&p_cnt, g_cnt);

    static bool attr_set = false;
    if (!attr_set) {
        cudaFuncSetAttribute(attn_kernel, cudaFuncAttributeMaxDynamicSharedMemorySize,
                             (2*64*KSTR + 64*SSTR) * (int)sizeof(float));
        attr_set = true;
    }

    // 1. attn rmsnorm
    rmsnorm_kernel<<<SEQ, 256>>>(x, anw, p_hn);
    // 2. qkv = hn @ wqkv^T   (tf32 tensor cores)
    gemm_tf32_kernel<false><<<dim3(QKVN/128, SEQ/128), 256>>>(
        p_hn, wqkv, nullptr, p_qkv, SEQ, QKVN, DM, 0);
    // 3. rope + split
    {
        int total = SEQ * (QKVN/2);
        rope_split_kernel<<<(total + 255)/256, 256>>>(freqs);
    }
    // 4. attention
    attn_kernel<<<dim3(SEQ/64, NH), 64, (2*64*KSTR + 64*SSTR)*(int)sizeof(float)>>>();
    // 5. h = x + y @ wo^T    (tf32)
    gemm_tf32_kernel<false><<<dim3(DM/128, SEQ/128), 256>>>(
        p_y, wo, x, p_h, SEQ, DM, DM, 0);
    // 6. ffn rmsnorm
    rmsnorm_kernel<<<SEQ, 256>>>(p_h, fnw, p_hf);
    // 7. gating
    cudaMemsetAsync(p_cnt, 0, NE*sizeof(int), 0);
    gating_kernel<<<SEQ, 256>>>(gate_w);
    // 8. MoE expert GEMMs (tf32, gathered, only selected experts)
    gemm_tf32_kernel<true><<<dim3(NI/128, SEQ/128, NE), 256>>>(
        p_hf, w1, nullptr, p_g1, 0, NI, DM, 1);
    gemm_tf32_kernel<true><<<dim3(NI/128, SEQ/128, NE), 256>>>(
        p_hf, w3, nullptr, p_g3, 0, NI, DM, 1);
    // 9. g = silu(g1) * g3
    {
        size_t n4 = (size_t)NSLOTS * NI / 4;
        silu_mul_kernel<<<(int)((n4 + 255)/256), 256>>>();
    }
    // 10. out_slot = g @ w2^T (tf32)
    gemm_tf32_kernel<true><<<dim3(DM/128, SEQ/128, NE), 256>>>(
        p_g1, w2, nullptr, p_os, 0, DM, NI, 0);
    // 11. combine
    combine_kernel<<<SEQ, 256>>>(out);
}

// round 3
// speedup vs baseline: 3.1766x; 2.0026x over previous
#include <cuda_runtime.h>
#include <math.h>
#include <stdint.h>

#define SEQ 2048
#define DM 1024
#define NH 16
#define NKV 4
#define HDIM 64
#define NE 8
#define NI 3584
#define QKVN 1536
#define NSLOTS (2*SEQ)

// ---------------- scratch (device globals; no allocations) ----------------
__device__ float g_hn[SEQ*DM];
__device__ float g_qkv[SEQ*QKVN];
__device__ float g_q[NH*SEQ*HDIM];
__device__ float g_k[NKV*SEQ*HDIM];
__device__ float g_v[NKV*SEQ*HDIM];
__device__ float g_y[SEQ*DM];
__device__ float g_h[SEQ*DM];
__device__ float g_hf[SEQ*DM];
__device__ int   g_cnt[NE];
__device__ int   g_slot[NE*SEQ];
__device__ float g_wslot[NSLOTS];
__device__ float g_g1[(size_t)NSLOTS*NI];
__device__ float g_g3[(size_t)NSLOTS*NI];
__device__ float g_os[(size_t)NSLOTS*DM];

// ---------------- helpers ---------------------------------------------------
__device__ __forceinline__ uint32_t f2tf32(float f) {
    uint32_t r;
    asm("cvt.rna.tf32.f32 %0, %1;" : "=r"(r) : "f"(f));
    return r;
}

__device__ __forceinline__ void mma_tf32(float c[4],
    uint32_t a0, uint32_t a1, uint32_t a2, uint32_t a3,
    uint32_t b0, uint32_t b1)
{
    asm volatile(
        "mma.sync.aligned.m16n8k8.row.col.f32.tf32.tf32.f32 "
        "{%0,%1,%2,%3}, {%4,%5,%6,%7}, {%8,%9}, {%0,%1,%2,%3};"
        : "+f"(c[0]), "+f"(c[1]), "+f"(c[2]), "+f"(c[3])
        : "r"(a0), "r"(a1), "r"(a2), "r"(a3), "r"(b0), "r"(b1));
}

__device__ __forceinline__ void cp_async16(uint32_t dst, const void* src, int sz) {
    asm volatile("cp.async.ca.shared.global [%0], [%1], 16, %2;"
                 :: "r"(dst), "l"(src), "r"(sz));
}
__device__ __forceinline__ void cp_commit() {
    asm volatile("cp.async.commit_group;");
}

// round fp32 bits to tf32 (round-half-away): add half-ulp of dropped field.
__device__ __forceinline__ uint32_t rnd13(float f) {
    return __float_as_uint(f) + 0x1000u;
}

// ---------------- rmsnorm ---------------------------------------------------
__global__ __launch_bounds__(256) void rmsnorm_kernel(
    const float* __restrict__ x, const float* __restrict__ w, float* __restrict__ o)
{
    int row = blockIdx.x;
    int tid = threadIdx.x;
    const float4* xr = (const float4*)(x + (size_t)row*DM);
    float4 v = xr[tid];
    float ss = v.x*v.x + v.y*v.y + v.z*v.z + v.w*v.w;
    __shared__ float red[8];
    #pragma unroll
    for (int ofs = 16; ofs > 0; ofs >>= 1) ss += __shfl_down_sync(0xffffffffu, ss, ofs);
    if ((tid & 31) == 0) red[tid >> 5] = ss;
    __syncthreads();
    __shared__ float sr;
    if (tid == 0) {
        float t = 0.f;
        #pragma unroll
        for (int i = 0; i < 8; i++) t += red[i];
        sr = rsqrtf(t / (float)DM + 1e-5f);
    }
    __syncthreads();
    float r = sr;
    const float4* wr = (const float4*)w;
    float4 wv = wr[tid];
    float4 out;
    out.x = v.x*r*wv.x; out.y = v.y*r*wv.y; out.z = v.z*r*wv.z; out.w = v.w*r*wv.w;
    ((float4*)(o + (size_t)row*DM))[tid] = out;
}

// ---------------- TF32 GEMM v3: cp.async 3-stage, 64x64 warp tiles ---------
// C[M,N] = A[M,K] * B[N,K]^T (+ optional resid).
// 128x128 block tile, BK=16, 128 threads (4 warps, 2x2), warp tile 64x64.
// smem layout [row][k] stride 20 (conflict-free: banks 20g+tg cover 0..31).
// GATHER: per-expert (blockIdx.z), A rows via slot list, C rows scattered.
#define SROW 20
#define STILE (128*SROW)
template<bool GATHER>
__global__ __launch_bounds__(128) void gemm_tf32_v3(
    const float* __restrict__ A, const float* __restrict__ B,
    const float* __restrict__ resid, float* __restrict__ C,
    int M, int N, int K, int shiftA)
{
    extern __shared__ float smem[];
    float* As = smem;              // [3][128][20]
    float* Bs = smem + 3*STILE;

    const int* sl = nullptr;
    if (GATHER) {
        int e = blockIdx.z;
        M = g_cnt[e];
        if ((int)blockIdx.y * 128 >= M) return;
        sl = g_slot + e * SEQ;
        B += (size_t)e * N * K;
    }
    int m0 = blockIdx.y * 128, n0 = blockIdx.x * 128;
    int tid = threadIdx.x;
    int warp = tid >> 5, lane = tid & 31;
    int g = lane >> 2, tg = lane & 3;
    int wm = (warp >> 1) * 64, wn = (warp & 1) * 64;

    uint32_t sA = (uint32_t)__cvta_generic_to_shared(As);
    uint32_t sB = (uint32_t)__cvta_generic_to_shared(Bs);

    float acc[4][8][4];
    #pragma unroll
    for (int i = 0; i < 4; i++)
        #pragma unroll
        for (int j = 0; j < 8; j++)
            #pragma unroll
            for (int q = 0; q < 4; q++) acc[i][j][q] = 0.f;

    int kTiles = K / 16;

    auto issue = [&](int stage, int kt) {
        #pragma unroll
        for (int c = 0; c < 4; c++) {
            int id = c * 128 + tid;
            int row = id >> 2;
            int kof = (id & 3) * 4;
            const float* srcA;
            int szA = 16;
            if (GATHER) {
                int gm = m0 + row;
                if (gm < M) {
                    srcA = A + (size_t)(sl[gm] >> shiftA) * K + kt*16 + kof;
                } else {
                    srcA = A; szA = 0;
                }
            } else {
                srcA = A + (size_t)(m0 + row) * K + kt*16 + kof;
            }
            cp_async16(sA + (uint32_t)(stage*STILE + row*SROW + kof)*4u, srcA, szA);
            const float* srcB = B + (size_t)(n0 + row) * K + kt*16 + kof;
            cp_async16(sB + (uint32_t)(stage*STILE + row*SROW + kof)*4u, srcB, 16);
        }
        cp_commit();
    };

    issue(0, 0);
    issue(1, 1);

    for (int kt = 0; kt < kTiles; kt++) {
        asm volatile("cp.async.wait_group %0;" :: "n"(1));
        __syncthreads();
        if (kt + 2 < kTiles) issue((kt + 2) % 3, kt + 2);
        else cp_commit();

        const float* Ab = As + (kt % 3) * STILE;
        const float* Bb = Bs + (kt % 3) * STILE;
        #pragma unroll
        for (int kk = 0; kk < 16; kk += 8) {
            uint32_t af[4][4];
            #pragma unroll
            for (int i = 0; i < 4; i++) {
                int mb = wm + i*16 + g;
                af[i][0] = rnd13(Ab[mb*SROW + kk + tg]);
                af[i][1] = rnd13(Ab[(mb+8)*SROW + kk + tg]);
                af[i][2] = rnd13(Ab[mb*SROW + kk + tg + 4]);
                af[i][3] = rnd13(Ab[(mb+8)*SROW + kk + tg + 4]);
            }
            #pragma unroll
            for (int j = 0; j < 8; j++) {
                int nb = wn + j*8 + g;
                uint32_t b0 = rnd13(Bb[nb*SROW + kk + tg]);
                uint32_t b1 = rnd13(Bb[nb*SROW + kk + tg + 4]);
                #pragma unroll
                for (int i = 0; i < 4; i++)
                    mma_tf32(acc[i][j], af[i][0], af[i][1], af[i][2], af[i][3], b0, b1);
            }
        }
    }
    asm volatile("cp.async.wait_group %0;" :: "n"(0));

    // epilogue
    #pragma unroll
    for (int i = 0; i < 4; i++) {
        int r0 = m0 + wm + i*16 + g;
        int r1 = r0 + 8;
        bool v0, v1;
        int row0, row1;
        if (GATHER) {
            v0 = r0 < M; v1 = r1 < M;
            row0 = v0 ? sl[r0] : 0;
            row1 = v1 ? sl[r1] : 0;
        } else {
            v0 = v1 = true; row0 = r0; row1 = r1;
        }
        #pragma unroll
        for (int j = 0; j < 8; j++) {
            int c0 = n0 + wn + j*8 + tg*2;
            if (v0) {
                float2 v; v.x = acc[i][j][0]; v.y = acc[i][j][1];
                if (resid) {
                    v.x += resid[(size_t)row0*N + c0];
                    v.y += resid[(size_t)row0*N + c0 + 1];
                }
                *(float2*)(C + (size_t)row0*N + c0) = v;
            }
            if (v1) {
                float2 v; v.x = acc[i][j][2]; v.y = acc[i][j][3];
                if (resid) {
                    v.x += resid[(size_t)row1*N + c0];
                    v.y += resid[(size_t)row1*N + c0 + 1];
                }
                *(float2*)(C + (size_t)row1*N + c0) = v;
            }
        }
    }
}

// ---------------- RoPE + QKV split ----------------------------------------
__global__ void rope_split_kernel(const float* __restrict__ freqs)
{
    int idx = blockIdx.x * blockDim.x + threadIdx.x;
    if (idx >= SEQ * (QKVN/2)) return;
    int t = idx / (QKVN/2);
    int col = (idx % (QKVN/2)) * 2;
    float x0 = g_qkv[(size_t)t*QKVN + col];
    float x1 = g_qkv[(size_t)t*QKVN + col + 1];
    if (col < DM) {
        int h = col >> 6, d = col & 63, p = d >> 1;
        float cs = freqs[((size_t)t*32 + p)*2 + 0];
        float sn = freqs[((size_t)t*32 + p)*2 + 1];
        float o0 = x0*cs - x1*sn;
        float o1 = x1*cs + x0*sn;
        size_t base = ((size_t)h*SEQ + t)*HDIM + d;
        g_q[base] = o0; g_q[base+1] = o1;
    } else if (col < DM + NKV*HDIM) {
        int c = col - DM;
        int kh = c >> 6, d = c & 63, p = d >> 1;
        float cs = freqs[((size_t)t*32 + p)*2 + 0];
        float sn = freqs[((size_t)t*32 + p)*2 + 1];
        float o0 = x0*cs - x1*sn;
        float o1 = x1*cs + x0*sn;
        size_t base = ((size_t)kh*SEQ + t)*HDIM + d;
        g_k[base] = o0; g_k[base+1] = o1;
    } else {
        int c = col - DM - NKV*HDIM;
        int vh = c >> 6, d = c & 63;
        size_t base = ((size_t)vh*SEQ + t)*HDIM + d;
        g_v[base] = x0; g_v[base+1] = x1;
    }
}

// ---------------- TF32 tensor-core flash attention (causal, GQA) -----------
// block = 128 thr (4 warps), each warp owns 16 query rows; qtile = 64.
// All smem natural row-major stride 68: every fragment access pattern
// hits banks (4g+tg) -> conflict-free.
#define ASTR 68
__global__ __launch_bounds__(128) void attn_tf32_kernel()
{
    extern __shared__ float sm[];
    float* Ks = sm;                 // [64][68]
    float* Vs = sm + 64*ASTR;       // [64][68]
    float* QP = sm + 2*64*ASTR;     // Q staging, then P per warp rows

    int qt = blockIdx.x, h = blockIdx.y;
    int kvh = h >> 2;
    int tid = threadIdx.x, warp = tid >> 5, lane = tid & 31;
    int g = lane >> 2, tg = lane & 3;
    int wq = warp * 16;
    int q0 = qt * 64;

    // stage Q (scaled by 1/8, rna->tf32)
    for (int i = tid; i < 64*16; i += 128) {
        int row = i >> 4, c4 = (i & 15) * 4;
        float4 v = *(const float4*)(g_q + ((size_t)h*SEQ + q0 + row)*HDIM + c4);
        QP[row*ASTR + c4 + 0] = __uint_as_float(f2tf32(v.x * 0.125f));
        QP[row*ASTR + c4 + 1] = __uint_as_float(f2tf32(v.y * 0.125f));
        QP[row*ASTR + c4 + 2] = __uint_as_float(f2tf32(v.z * 0.125f));
        QP[row*ASTR + c4 + 3] = __uint_as_float(f2tf32(v.w * 0.125f));
    }
    __syncthreads();
    uint32_t aq[8][4];
    #pragma unroll
    for (int kk = 0; kk < 8; kk++) {
        aq[kk][0] = __float_as_uint(QP[(wq+g)*ASTR + kk*8 + tg]);
        aq[kk][1] = __float_as_uint(QP[(wq+g+8)*ASTR + kk*8 + tg]);
        aq[kk][2] = __float_as_uint(QP[(wq+g)*ASTR + kk*8 + tg + 4]);
        aq[kk][3] = __float_as_uint(QP[(wq+g+8)*ASTR + kk*8 + tg + 4]);
    }
    __syncthreads();

    float oc[8][4];
    #pragma unroll
    for (int j = 0; j < 8; j++)
        #pragma unroll
        for (int q = 0; q < 4; q++) oc[j][q] = 0.f;
    float mrow[2] = {-1e30f, -1e30f};
    float lrow[2] = {0.f, 0.f};

    for (int kt = 0; kt <= qt; kt++) {
        // stage K, V tiles (rna->tf32)
        for (int i = tid; i < 64*16; i += 128) {
            int row = i >> 4, c4 = (i & 15) * 4;
            size_t base = ((size_t)kvh*SEQ + kt*64 + row)*HDIM + c4;
            float4 kv = *(const float4*)(g_k + base);
            float4 vv = *(const float4*)(g_v + base);
            Ks[row*ASTR + c4 + 0] = __uint_as_float(f2tf32(kv.x));
            Ks[row*ASTR + c4 + 1] = __uint_as_float(f2tf32(kv.y));
            Ks[row*ASTR + c4 + 2] = __uint_as_float(f2tf32(kv.z));
            Ks[row*ASTR + c4 + 3] = __uint_as_float(f2tf32(kv.w));
            Vs[row*ASTR + c4 + 0] = __uint_as_float(f2tf32(vv.x));
            Vs[row*ASTR + c4 + 1] = __uint_as_float(f2tf32(vv.y));
            Vs[row*ASTR + c4 + 2] = __uint_as_float(f2tf32(vv.z));
            Vs[row*ASTR + c4 + 3] = __uint_as_float(f2tf32(vv.w));
        }
        __syncthreads();

        // S = Q @ K^T
        float sc[8][4];
        #pragma unroll
        for (int j = 0; j < 8; j++)
            #pragma unroll
            for (int q = 0; q < 4; q++) sc[j][q] = 0.f;
        #pragma unroll
        for (int kk = 0; kk < 8; kk++) {
            #pragma unroll
            for (int j = 0; j < 8; j++) {
                uint32_t b0 = __float_as_uint(Ks[(j*8+g)*ASTR + kk*8 + tg]);
                uint32_t b1 = __float_as_uint(Ks[(j*8+g)*ASTR + kk*8 + tg + 4]);
                mma_tf32(sc[j], aq[kk][0], aq[kk][1], aq[kk][2], aq[kk][3], b0, b1);
            }
        }

        // causal mask on diagonal tile
        if (kt == qt) {
            int r0g = q0 + wq + g, r1g = r0g + 8;
            #pragma unroll
            for (int j = 0; j < 8; j++) {
                int c0 = kt*64 + j*8 + tg*2;
                if (c0     > r0g) sc[j][0] = -1e30f;
                if (c0 + 1 > r0g) sc[j][1] = -1e30f;
                if (c0     > r1g) sc[j][2] = -1e30f;
                if (c0 + 1 > r1g) sc[j][3] = -1e30f;
            }
        }

        // online softmax
        float mx0 = -1e30f, mx1 = -1e30f;
        #pragma unroll
        for (int j = 0; j < 8; j++) {
            mx0 = fmaxf(mx0, fmaxf(sc[j][0], sc[j][1]));
            mx1 = fmaxf(mx1, fmaxf(sc[j][2], sc[j][3]));
        }
        mx0 = fmaxf(mx0, __shfl_xor_sync(0xffffffffu, mx0, 1));
        mx0 = fmaxf(mx0, __shfl_xor_sync(0xffffffffu, mx0, 2));
        mx1 = fmaxf(mx1, __shfl_xor_sync(0xffffffffu, mx1, 1));
        mx1 = fmaxf(mx1, __shfl_xor_sync(0xffffffffu, mx1, 2));
        float mn0 = fmaxf(mrow[0], mx0), mn1 = fmaxf(mrow[1], mx1);
        float s0 = __expf(mrow[0] - mn0), s1 = __expf(mrow[1] - mn1);
        float ls0 = 0.f, ls1 = 0.f;
        #pragma unroll
        for (int j = 0; j < 8; j++) {
            sc[j][0] = __expf(sc[j][0] - mn0);
            sc[j][1] = __expf(sc[j][1] - mn0);
            sc[j][2] = __expf(sc[j][2] - mn1);
            sc[j][3] = __expf(sc[j][3] - mn1);
            ls0 += sc[j][0] + sc[j][1];
            ls1 += sc[j][2] + sc[j][3];
        }
        ls0 += __shfl_xor_sync(0xffffffffu, ls0, 1);
        ls0 += __shfl_xor_sync(0xffffffffu, ls0, 2);
        ls1 += __shfl_xor_sync(0xffffffffu, ls1, 1);
        ls1 += __shfl_xor_sync(0xffffffffu, ls1, 2);
        lrow[0] = lrow[0]*s0 + ls0;
        lrow[1] = lrow[1]*s1 + ls1;
        mrow[0] = mn0; mrow[1] = mn1;
        #pragma unroll
        for (int j = 0; j < 8; j++) {
            oc[j][0] *= s0; oc[j][1] *= s0;
            oc[j][2] *= s1; oc[j][3] *= s1;
        }

        // write P (tf32-rounded) to warp-private QP rows
        #pragma unroll
        for (int j = 0; j < 8; j++) {
            float2 p0, p1;
            p0.x = __uint_as_float(f2tf32(sc[j][0]));
            p0.y = __uint_as_float(f2tf32(sc[j][1]));
            p1.x = __uint_as_float(f2tf32(sc[j][2]));
            p1.y = __uint_as_float(f2tf32(sc[j][3]));
            *(float2*)&QP[(wq+g)*ASTR + j*8 + tg*2]   = p0;
            *(float2*)&QP[(wq+g+8)*ASTR + j*8 + tg*2] = p1;
        }
        __syncwarp();

        // O += P @ V
        #pragma unroll
        for (int kk = 0; kk < 8; kk++) {
            uint32_t a0 = __float_as_uint(QP[(wq+g)*ASTR + kk*8 + tg]);
            uint32_t a1 = __float_as_uint(QP[(wq+g+8)*ASTR + kk*8 + tg]);
            uint32_t a2 = __float_as_uint(QP[(wq+g)*ASTR + kk*8 + tg + 4]);
            uint32_t a3 = __float_as_uint(QP[(wq+g+8)*ASTR + kk*8 + tg + 4]);
            #pragma unroll
            for (int j = 0; j < 8; j++) {
                uint32_t b0 = __float_as_uint(Vs[(kk*8+tg)*ASTR + j*8 + g]);
                uint32_t b1 = __float_as_uint(Vs[(kk*8+tg+4)*ASTR + j*8 + g]);
                mma_tf32(oc[j], a0, a1, a2, a3, b0, b1);
            }
        }
        __syncthreads();
    }

    float inv0 = 1.f / lrow[0], inv1 = 1.f / lrow[1];
    #pragma unroll
    for (int j = 0; j < 8; j++) {
        int col = h*HDIM + j*8 + tg*2;
        float2 v0, v1;
        v0.x = oc[j][0]*inv0; v0.y = oc[j][1]*inv0;
        v1.x = oc[j][2]*inv1; v1.y = oc[j][3]*inv1;
        *(float2*)(g_y + (size_t)(q0+wq+g)*DM + col)   = v0;
        *(float2*)(g_y + (size_t)(q0+wq+g+8)*DM + col) = v1;
    }
}

// ---------------- gating: softmax over 8 experts, top-2 -------------------
__global__ __launch_bounds__(256) void gating_kernel(const float* __restrict__ gw)
{
    int t = blockIdx.x;
    int tid = threadIdx.x;
    int e = tid >> 5, lane = tid & 31;
    float s = 0.f;
    const float* hr = g_hf + (size_t)t*DM;
    const float* wr = gw + (size_t)e*DM;
    for (int d = lane; d < DM; d += 32) s += hr[d]*wr[d];
    #pragma unroll
    for (int ofs = 16; ofs > 0; ofs >>= 1) s += __shfl_down_sync(0xffffffffu, s, ofs);
    __shared__ float lg[NE];
    if (lane == 0) lg[e] = s;
    __syncthreads();
    if (tid == 0) {
        float mx = lg[0];
        #pragma unroll
        for (int i = 1; i < NE; i++) mx = fmaxf(mx, lg[i]);
        float p[NE]; float den = 0.f;
        #pragma unroll
        for (int i = 0; i < NE; i++) { p[i] = expf(lg[i]-mx); den += p[i]; }
        #pragma unroll
        for (int i = 0; i < NE; i++) p[i] /= den;
        int i1 = 0;
        #pragma unroll
        for (int i = 1; i < NE; i++) if (p[i] > p[i1]) i1 = i;
        int i2 = (i1 == 0) ? 1 : 0;
        #pragma unroll
        for (int i = 0; i < NE; i++) if (i != i1 && p[i] > p[i2]) i2 = i;
        float w1 = p[i1], w2 = p[i2];
        float sw = w1 + w2;
        w1 /= sw; w2 /= sw;
        int pos1 = atomicAdd(&g_cnt[i1], 1);
        g_slot[i1*SEQ + pos1] = 2*t;
        g_wslot[2*t] = w1;
        int pos2 = atomicAdd(&g_cnt[i2], 1);
        g_slot[i2*SEQ + pos2] = 2*t + 1;
        g_wslot[2*t+1] = w2;
    }
}

// ---------------- silu(g1)*g3 -> g1 ----------------------------------------
__global__ void silu_mul_kernel()
{
    size_t i = (size_t)blockIdx.x * blockDim.x + threadIdx.x;
    size_t n4 = (size_t)NSLOTS * NI / 4;
    if (i >= n4) return;
    float4 a = ((const float4*)g_g1)[i];
    float4 b = ((const float4*)g_g3)[i];
    float4 o;
    o.x = (a.x / (1.f + __expf(-a.x))) * b.x;
    o.y = (a.y / (1.f + __expf(-a.y))) * b.y;
    o.z = (a.z / (1.f + __expf(-a.z))) * b.z;
    o.w = (a.w / (1.f + __expf(-a.w))) * b.w;
    ((float4*)g_g1)[i] = o;
}

// ---------------- final combine ---------------------------------------------
__global__ __launch_bounds__(256) void combine_kernel(float* __restrict__ out)
{
    int t = blockIdx.x;
    int tid = threadIdx.x;
    float w0 = g_wslot[2*t], w1 = g_wslot[2*t+1];
    float4 hv = ((const float4*)(g_h + (size_t)t*DM))[tid];
    float4 a = ((const float4*)(g_os + (size_t)(2*t)*DM))[tid];
    float4 b = ((const float4*)(g_os + (size_t)(2*t+1)*DM))[tid];
    float4 o;
    o.x = hv.x + w0*a.x + w1*b.x;
    o.y = hv.y + w0*a.y + w1*b.y;
    o.z = hv.z + w0*a.z + w1*b.z;
    o.w = hv.w + w0*a.w + w1*b.w;
    ((float4*)(out + (size_t)t*DM))[tid] = o;
}

// ---------------- host launch ----------------------------------------------
#define GEMM_SMEM (2*3*STILE*(int)sizeof(float))
#define ATTN_SMEM (3*64*ASTR*(int)sizeof(float))

extern "C" void kernel_launch(void* const* d_in, const int* in_sizes, int n_in,
                              void* d_out, int out_size)
{
    const float* x      = (const float*)d_in[0];
    const float* wqkv   = (const float*)d_in[1];
    const float* wo     = (const float*)d_in[2];
    const float* gate_w = (const float*)d_in[3];
    const float* w1     = (const float*)d_in[4];
    const float* w2     = (const float*)d_in[5];
    const float* w3     = (const float*)d_in[6];
    const float* anw    = (const float*)d_in[7];
    const float* fnw    = (const float*)d_in[8];
    const float* freqs  = (const float*)d_in[9];
    float* out = (float*)d_out;

    float *p_hn, *p_qkv, *p_y, *p_h, *p_hf, *p_g1, *p_g3, *p_os;
    int *p_cnt;
    cudaGetSymbolAddress((void**)&p_hn,  g_hn);
    cudaGetSymbolAddress((void**)&p_qkv, g_qkv);
    cudaGetSymbolAddress((void**)&p_y,   g_y);
    cudaGetSymbolAddress((void**)&p_h,   g_h);
    cudaGetSymbolAddress((void**)&p_hf,  g_hf);
    cudaGetSymbolAddress((void**)&p_g1,  g_g1);
    cudaGetSymbolAddress((void**)&p_g3,  g_g3);
    cudaGetSymbolAddress((void**)&p_os,  g_os);
    cudaGetSymbolAddress((void**)&p_cnt, g_cnt);

    static bool attr_set = false;
    if (!attr_set) {
        cudaFuncSetAttribute(attn_tf32_kernel,
            cudaFuncAttributeMaxDynamicSharedMemorySize, ATTN_SMEM);
        cudaFuncSetAttribute(gemm_tf32_v3<false>,
            cudaFuncAttributeMaxDynamicSharedMemorySize, GEMM_SMEM);
        cudaFuncSetAttribute(gemm_tf32_v3<true>,
            cudaFuncAttributeMaxDynamicSharedMemorySize, GEMM_SMEM);
        attr_set = true;
    }

    // 1. attn rmsnorm
    rmsnorm_kernel<<<SEQ, 256>>>(x, anw, p_hn);
    // 2. qkv = hn @ wqkv^T
    gemm_tf32_v3<false><<<dim3(QKVN/128, SEQ/128), 128, GEMM_SMEM>>>(
        p_hn, wqkv, nullptr, p_qkv, SEQ, QKVN, DM, 0);
    // 3. rope + split
    {
        int total = SEQ * (QKVN/2);
        rope_split_kernel<<<(total + 255)/256, 256>>>(freqs);
    }
    // 4. attention (tf32 tensor cores)
    attn_tf32_kernel<<<dim3(SEQ/64, NH), 128, ATTN_SMEM>>>();
    // 5. h = x + y @ wo^T
    gemm_tf32_v3<false><<<dim3(DM/128, SEQ/128), 128, GEMM_SMEM>>>(
        p_y, wo, x, p_h, SEQ, DM, DM, 0);
    // 6. ffn rmsnorm
    rmsnorm_kernel<<<SEQ, 256>>>(p_h, fnw, p_hf);
    // 7. gating
    cudaMemsetAsync(p_cnt, 0, NE*sizeof(int), 0);
    gating_kernel<<<SEQ, 256>>>(gate_w);
    // 8. MoE expert GEMMs
    gemm_tf32_v3<true><<<dim3(NI/128, SEQ/128, NE), 128, GEMM_SMEM>>>(
        p_hf, w1, nullptr, p_g1, 0, NI, DM, 1);
    gemm_tf32_v3<true><<<dim3(NI/128, SEQ/128, NE), 128, GEMM_SMEM>>>(
        p_hf, w3, nullptr, p_g3, 0, NI, DM, 1);
    // 9. g = silu(g1) * g3
    {
        size_t n4 = (size_t)NSLOTS * NI / 4;
        silu_mul_kernel<<<(int)((n4 + 255)/256), 256>>>();
    }
    // 10. out_slot = g @ w2^T
    gemm_tf32_v3<true><<<dim3(DM/128, SEQ/128, NE), 128, GEMM_SMEM>>>(
        p_g1, w2, nullptr, p_os, 0, DM, NI, 0);
    // 11. combine
    combine_kernel<<<SEQ, 256>>>(out);
}

// round 5
// speedup vs baseline: 5.0105x; 1.5773x over previous
#include <cuda_runtime.h>
#include <cuda_bf16.h>
#include <math.h>
#include <stdint.h>

#define SEQ 2048
#define DM 1024
#define NH 16
#define NKV 4
#define HDIM 64
#define NE 8
#define NI 3584
#define QKVN 1536
#define NSLOTS (2*SEQ)

typedef __nv_bfloat16 bf16;

// ---------------- scratch (device globals; no allocations) ----------------
__device__ bf16  g_wqkv_bf[QKVN*DM];
__device__ bf16  g_wo_bf[DM*DM];
__device__ bf16  g_w1_bf[(size_t)NE*NI*DM];
__device__ bf16  g_w3_bf[(size_t)NE*NI*DM];
__device__ bf16  g_w2_bf[(size_t)NE*DM*NI];
__device__ bf16  g_hn_bf[SEQ*DM];
__device__ float g_qkv[SEQ*QKVN];
__device__ float g_q[NH*SEQ*HDIM];
__device__ float g_k[NKV*SEQ*HDIM];
__device__ float g_v[NKV*SEQ*HDIM];
__device__ bf16  g_y_bf[SEQ*DM];
__device__ float g_h[SEQ*DM];
__device__ float g_hf[SEQ*DM];
__device__ bf16  g_hf_bf[SEQ*DM];
__device__ int   g_cnt[NE];
__device__ int   g_slot[NE*SEQ];
__device__ float g_wslot[NSLOTS];
__device__ bf16  g_gb[(size_t)NSLOTS*NI];
__device__ float g_os[(size_t)NSLOTS*DM];

// ---------------- helpers ---------------------------------------------------
__device__ __forceinline__ uint32_t f2tf32(float f) {
    uint32_t r;
    asm("cvt.rna.tf32.f32 %0, %1;" : "=r"(r) : "f"(f));
    return r;
}
__device__ __forceinline__ void mma_tf32(float c[4],
    uint32_t a0, uint32_t a1, uint32_t a2, uint32_t a3,
    uint32_t b0, uint32_t b1)
{
    asm volatile(
        "mma.sync.aligned.m16n8k8.row.col.f32.tf32.tf32.f32 "
        "{%0,%1,%2,%3}, {%4,%5,%6,%7}, {%8,%9}, {%0,%1,%2,%3};"
        : "+f"(c[0]), "+f"(c[1]), "+f"(c[2]), "+f"(c[3])
        : "r"(a0), "r"(a1), "r"(a2), "r"(a3), "r"(b0), "r"(b1));
}
__device__ __forceinline__ void mma_bf16(float c[4],
    uint32_t a0, uint32_t a1, uint32_t a2, uint32_t a3,
    uint32_t b0, uint32_t b1)
{
    asm volatile(
        "mma.sync.aligned.m16n8k16.row.col.f32.bf16.bf16.f32 "
        "{%0,%1,%2,%3}, {%4,%5,%6,%7}, {%8,%9}, {%0,%1,%2,%3};"
        : "+f"(c[0]), "+f"(c[1]), "+f"(c[2]), "+f"(c[3])
        : "r"(a0), "r"(a1), "r"(a2), "r"(a3), "r"(b0), "r"(b1));
}
__device__ __forceinline__ void ldsm4(uint32_t r[4], uint32_t addr) {
    asm volatile("ldmatrix.sync.aligned.m8n8.x4.shared.b16 {%0,%1,%2,%3}, [%4];"
                 : "=r"(r[0]), "=r"(r[1]), "=r"(r[2]), "=r"(r[3]) : "r"(addr));
}
__device__ __forceinline__ void cpa(uint32_t dst, const void* src, int sz) {
    asm volatile("cp.async.cg.shared.global [%0], [%1], 16, %2;"
                 :: "r"(dst), "l"(src), "r"(sz));
}

// ---------------- fp32 -> bf16 convert --------------------------------------
__global__ void f2bf_kernel(const float4* __restrict__ s, uint2* __restrict__ d, int n4)
{
    int i = blockIdx.x * blockDim.x + threadIdx.x;
    if (i >= n4) return;
    float4 v = s[i];
    __nv_bfloat162 lo = __floats2bfloat162_rn(v.x, v.y);
    __nv_bfloat162 hi = __floats2bfloat162_rn(v.z, v.w);
    uint2 o;
    o.x = *(uint32_t*)&lo;
    o.y = *(uint32_t*)&hi;
    d[i] = o;
}

// ---------------- rmsnorm (bf16 out + optional fp32 out) -------------------
__global__ __launch_bounds__(256) void rmsnorm_kernel(
    const float* __restrict__ x, const float* __restrict__ w,
    bf16* __restrict__ obf, float* __restrict__ ofp)
{
    int row = blockIdx.x;
    int tid = threadIdx.x;
    const float4* xr = (const float4*)(x + (size_t)row*DM);
    float4 v = xr[tid];
    float ss = v.x*v.x + v.y*v.y + v.z*v.z + v.w*v.w;
    __shared__ float red[8];
    #pragma unroll
    for (int ofs = 16; ofs > 0; ofs >>= 1) ss += __shfl_down_sync(0xffffffffu, ss, ofs);
    if ((tid & 31) == 0) red[tid >> 5] = ss;
    __syncthreads();
    __shared__ float sr;
    if (tid == 0) {
        float t = 0.f;
        #pragma unroll
        for (int i = 0; i < 8; i++) t += red[i];
        sr = rsqrtf(t / (float)DM + 1e-5f);
    }
    __syncthreads();
    float r = sr;
    float4 wv = ((const float4*)w)[tid];
    float4 o;
    o.x = v.x*r*wv.x; o.y = v.y*r*wv.y; o.z = v.z*r*wv.z; o.w = v.w*r*wv.w;
    __nv_bfloat162 lo = __floats2bfloat162_rn(o.x, o.y);
    __nv_bfloat162 hi = __floats2bfloat162_rn(o.z, o.w);
    uint2 ob; ob.x = *(uint32_t*)&lo; ob.y = *(uint32_t*)&hi;
    *(uint2*)(obf + (size_t)row*DM + tid*4) = ob;
    if (ofp) ((float4*)(ofp + (size_t)row*DM))[tid] = o;
}

// ---------------- bf16 HMMA GEMM: C[M,N] = A @ B^T (+resid) ----------------
// 128x128x64 tiles, 256 threads (8 warps, 2x4), warp tile 64x32,
// mma m16n8k16 bf16, 3-stage cp.async, XOR-swizzled smem + ldmatrix.
// GATHER: per-expert blockIdx.z; A row = slot>>shiftA, C row = slot.
#define GSTG 16384
template<bool GATHER>
__global__ __launch_bounds__(256) void gemm_bf(
    const bf16* __restrict__ A, const bf16* __restrict__ B,
    const float* __restrict__ resid, float* __restrict__ C,
    int M, int N, int K, int shiftA)
{
    extern __shared__ char smem[];
    const int* sl = nullptr;
    if (GATHER) {
        int e = blockIdx.z;
        M = g_cnt[e];
        if ((int)blockIdx.y * 128 >= M) return;
        sl = g_slot + e * SEQ;
        B += (size_t)e * N * K;
    }
    int m0 = blockIdx.y * 128, n0 = blockIdx.x * 128;
    int tid = threadIdx.x, warp = tid >> 5, lane = tid & 31;
    int wm = (warp >> 2) * 64, wn = (warp & 3) * 32;
    uint32_t sbase = (uint32_t)__cvta_generic_to_shared(smem);
    uint32_t aoff[3], boff[3];
    #pragma unroll
    for (int s = 0; s < 3; s++) {
        aoff[s] = sbase + s*GSTG;
        boff[s] = sbase + 3*GSTG + s*GSTG;
    }

    // loader: thread -> row tid>>1, segs (tid&1)*4 .. +3
    int lrow = tid >> 1;
    int lsg  = (tid & 1) * 4;
    const bf16* Arow; int szA = 16;
    if (GATHER) {
        int gm = m0 + lrow;
        if (gm < M) Arow = A + (size_t)(sl[gm] >> shiftA) * K;
        else { Arow = A; szA = 0; }
    } else {
        Arow = A + (size_t)(m0 + lrow) * K;
    }
    const bf16* Brow = B + (size_t)(n0 + lrow) * K;
    uint32_t dsw = (uint32_t)lrow * 128u;
    int rxor = lrow & 7;

    float acc[4][4][4];
    #pragma unroll
    for (int i = 0; i < 4; i++)
        #pragma unroll
        for (int j = 0; j < 4; j++)
            #pragma unroll
            for (int q = 0; q < 4; q++) acc[i][j][q] = 0.f;

    int CC = K / 64;
    auto loadChunk = [&](int c) {
        int s = c % 3;
        const char* pa = (const char*)(Arow + c*64);
        const char* pb = (const char*)(Brow + c*64);
        #pragma unroll
        for (int i = 0; i < 4; i++) {
            int seg = lsg + i;
            uint32_t o = dsw + (uint32_t)((seg ^ rxor) * 16);
            cpa(aoff[s] + o, pa + seg*16, szA);
            cpa(boff[s] + o, pb + seg*16, 16);
        }
        asm volatile("cp.async.commit_group;" ::: "memory");
    };
    loadChunk(0);
    if (CC > 1) loadChunk(1);

    int lt = lane >> 3;            // 0..3 tile index
    int rl = lane & 7;
    int th = (lt & 1) * 8;         // +8 row within 16-tile
    int ts = lane >> 4;            // seg half

    for (int c = 0; c < CC; c++) {
        if (c + 1 < CC) asm volatile("cp.async.wait_group 1;" ::: "memory");
        else            asm volatile("cp.async.wait_group 0;" ::: "memory");
        __syncthreads();
        if (c + 2 < CC) loadChunk(c + 2);

        uint32_t Ab = aoff[c % 3], Bb = boff[c % 3];
        #pragma unroll
        for (int kk = 0; kk < 4; kk++) {
            uint32_t af[4][4], bf[2][4];
            #pragma unroll
            for (int i = 0; i < 4; i++) {
                int row = wm + i*16 + th + rl;
                int seg = 2*kk + ts;
                ldsm4(af[i], Ab + row*128 + ((seg ^ (row & 7)) << 4));
            }
            #pragma unroll
            for (int j = 0; j < 2; j++) {
                int nr = wn + j*16 + th + rl;
                int seg = 2*kk + ts;
                ldsm4(bf[j], Bb + nr*128 + ((seg ^ (nr & 7)) << 4));
            }
            #pragma unroll
            for (int i = 0; i < 4; i++)
                #pragma unroll
                for (int jn = 0; jn < 4; jn++) {
                    int jj = jn >> 1, hi = jn & 1;
                    mma_bf16(acc[i][jn], af[i][0], af[i][1], af[i][2], af[i][3],
                             bf[jj][hi], bf[jj][hi+2]);
                }
        }
        __syncthreads();
    }

    // epilogue
    int g = lane >> 2, tg = lane & 3;
    #pragma unroll
    for (int i = 0; i < 4; i++) {
        int r0 = m0 + wm + i*16 + g;
        int r1 = r0 + 8;
        bool v0, v1;
        int row0, row1;
        if (GATHER) {
            v0 = r0 < M; v1 = r1 < M;
            row0 = v0 ? sl[r0] : 0;
            row1 = v1 ? sl[r1] : 0;
        } else {
            v0 = v1 = true; row0 = r0; row1 = r1;
        }
        #pragma unroll
        for (int j = 0; j < 4; j++) {
            int c0 = n0 + wn + j*8 + tg*2;
            if (v0) {
                float2 v; v.x = acc[i][j][0]; v.y = acc[i][j][1];
                if (resid) {
                    v.x += resid[(size_t)row0*N + c0];
                    v.y += resid[(size_t)row0*N + c0 + 1];
                }
                *(float2*)(C + (size_t)row0*N + c0) = v;
            }
            if (v1) {
                float2 v; v.x = acc[i][j][2]; v.y = acc[i][j][3];
                if (resid) {
                    v.x += resid[(size_t)row1*N + c0];
                    v.y += resid[(size_t)row1*N + c0 + 1];
                }
                *(float2*)(C + (size_t)row1*N + c0) = v;
            }
        }
    }
}

// ---------------- fused MoE w1/w3 GEMM + silu*mul (bf16 out) ---------------
__global__ __launch_bounds__(256) void gemm_w13(
    const bf16* __restrict__ A, const bf16* __restrict__ B1,
    const bf16* __restrict__ B3)
{
    extern __shared__ char smem[];
    int e = blockIdx.z;
    int M = g_cnt[e];
    if ((int)blockIdx.y * 128 >= M) return;
    const int* sl = g_slot + e * SEQ;
    B1 += (size_t)e * NI * DM;
    B3 += (size_t)e * NI * DM;

    int m0 = blockIdx.y * 128, n0 = blockIdx.x * 128;
    int tid = threadIdx.x, warp = tid >> 5, lane = tid & 31;
    int wm = (warp >> 2) * 64, wn = (warp & 3) * 32;
    uint32_t sbase = (uint32_t)__cvta_generic_to_shared(smem);
    uint32_t aoff[3], b1off[3], b3off[3];
    #pragma unroll
    for (int s = 0; s < 3; s++) {
        aoff[s]  = sbase + s*GSTG;
        b1off[s] = sbase + 3*GSTG + s*GSTG;
        b3off[s] = sbase + 6*GSTG + s*GSTG;
    }

    int lrow = tid >> 1;
    int lsg  = (tid & 1) * 4;
    const bf16* Arow; int szA = 16;
    {
        int gm = m0 + lrow;
        if (gm < M) Arow = A + (size_t)(sl[gm] >> 1) * DM;
        else { Arow = A; szA = 0; }
    }
    const bf16* B1row = B1 + (size_t)(n0 + lrow) * DM;
    const bf16* B3row = B3 + (size_t)(n0 + lrow) * DM;
    uint32_t dsw = (uint32_t)lrow * 128u;
    int rxor = lrow & 7;

    float ac1[4][4][4], ac3[4][4][4];
    #pragma unroll
    for (int i = 0; i < 4; i++)
        #pragma unroll
        for (int j = 0; j < 4; j++)
            #pragma unroll
            for (int q = 0; q < 4; q++) { ac1[i][j][q] = 0.f; ac3[i][j][q] = 0.f; }

    const int CC = DM / 64;
    auto loadChunk = [&](int c) {
        int s = c % 3;
        const char* pa  = (const char*)(Arow  + c*64);
        const char* pb1 = (const char*)(B1row + c*64);
        const char* pb3 = (const char*)(B3row + c*64);
        #pragma unroll
        for (int i = 0; i < 4; i++) {
            int seg = lsg + i;
            uint32_t o = dsw + (uint32_t)((seg ^ rxor) * 16);
            cpa(aoff[s]  + o, pa  + seg*16, szA);
            cpa(b1off[s] + o, pb1 + seg*16, 16);
            cpa(b3off[s] + o, pb3 + seg*16, 16);
        }
        asm volatile("cp.async.commit_group;" ::: "memory");
    };
    loadChunk(0);
    loadChunk(1);

    int lt = lane >> 3, rl = lane & 7;
    int th = (lt & 1) * 8;
    int ts = lane >> 4;

    for (int c = 0; c < CC; c++) {
        if (c + 1 < CC) asm volatile("cp.async.wait_group 1;" ::: "memory");
        else            asm volatile("cp.async.wait_group 0;" ::: "memory");
        __syncthreads();
        if (c + 2 < CC) loadChunk(c + 2);

        uint32_t Ab = aoff[c % 3], B1b = b1off[c % 3], B3b = b3off[c % 3];
        #pragma unroll
        for (int kk = 0; kk < 4; kk++) {
            uint32_t af[4][4], f1[2][4], f3[2][4];
            #pragma unroll
            for (int i = 0; i < 4; i++) {
                int row = wm + i*16 + th + rl;
                int seg = 2*kk + ts;
                ldsm4(af[i], Ab + row*128 + ((seg ^ (row & 7)) << 4));
            }
            #pragma unroll
            for (int j = 0; j < 2; j++) {
                int nr = wn + j*16 + th + rl;
                int seg = 2*kk + ts;
                ldsm4(f1[j], B1b + nr*128 + ((seg ^ (nr & 7)) << 4));
                ldsm4(f3[j], B3b + nr*128 + ((seg ^ (nr & 7)) << 4));
            }
            #pragma unroll
            for (int i = 0; i < 4; i++)
                #pragma unroll
                for (int jn = 0; jn < 4; jn++) {
                    int jj = jn >> 1, hi = jn & 1;
                    mma_bf16(ac1[i][jn], af[i][0], af[i][1], af[i][2], af[i][3],
                             f1[jj][hi], f1[jj][hi+2]);
                    mma_bf16(ac3[i][jn], af[i][0], af[i][1], af[i][2], af[i][3],
                             f3[jj][hi], f3[jj][hi+2]);
                }
        }
        __syncthreads();
    }

    // epilogue: silu(ac1)*ac3 -> bf16 scattered rows
    int g = lane >> 2, tg = lane & 3;
    #pragma unroll
    for (int i = 0; i < 4; i++) {
        int r0 = m0 + wm + i*16 + g;
        int r1 = r0 + 8;
        bool v0 = r0 < M, v1 = r1 < M;
        int row0 = v0 ? sl[r0] : 0;
        int row1 = v1 ? sl[r1] : 0;
        #pragma unroll
        for (int j = 0; j < 4; j++) {
            int c0 = n0 + wn + j*8 + tg*2;
            if (v0) {
                float a0 = ac1[i][j][0], a1 = ac1[i][j][1];
                float u0 = a0 / (1.f + __expf(-a0)) * ac3[i][j][0];
                float u1 = a1 / (1.f + __expf(-a1)) * ac3[i][j][1];
                *(__nv_bfloat162*)(g_gb + (size_t)row0*NI + c0) = __floats2bfloat162_rn(u0, u1);
            }
            if (v1) {
                float a0 = ac1[i][j][2], a1 = ac1[i][j][3];
                float u0 = a0 / (1.f + __expf(-a0)) * ac3[i][j][2];
                float u1 = a1 / (1.f + __expf(-a1)) * ac3[i][j][3];
                *(__nv_bfloat162*)(g_gb + (size_t)row1*NI + c0) = __floats2bfloat162_rn(u0, u1);
            }
        }
    }
}

// ---------------- RoPE + QKV split ----------------------------------------
__global__ void rope_split_kernel(const float* __restrict__ freqs)
{
    int idx = blockIdx.x * blockDim.x + threadIdx.x;
    if (idx >= SEQ * (QKVN/2)) return;
    int t = idx / (QKVN/2);
    int col = (idx % (QKVN/2)) * 2;
    float x0 = g_qkv[(size_t)t*QKVN + col];
    float x1 = g_qkv[(size_t)t*QKVN + col + 1];
    if (col < DM) {
        int h = col >> 6, d = col & 63, p = d >> 1;
        float cs = freqs[((size_t)t*32 + p)*2 + 0];
        float sn = freqs[((size_t)t*32 + p)*2 + 1];
        float o0 = x0*cs - x1*sn;
        float o1 = x1*cs + x0*sn;
        size_t base = ((size_t)h*SEQ + t)*HDIM + d;
        g_q[base] = o0; g_q[base+1] = o1;
    } else if (col < DM + NKV*HDIM) {
        int c = col - DM;
        int kh = c >> 6, d = c & 63, p = d >> 1;
        float cs = freqs[((size_t)t*32 + p)*2 + 0];
        float sn = freqs[((size_t)t*32 + p)*2 + 1];
        float o0 = x0*cs - x1*sn;
        float o1 = x1*cs + x0*sn;
        size_t base = ((size_t)kh*SEQ + t)*HDIM + d;
        g_k[base] = o0; g_k[base+1] = o1;
    } else {
        int c = col - DM - NKV*HDIM;
        int vh = c >> 6, d = c & 63;
        size_t base = ((size_t)vh*SEQ + t)*HDIM + d;
        g_v[base] = x0; g_v[base+1] = x1;
    }
}

// ---------------- TF32 tensor-core flash attention (causal, GQA) -----------
#define ASTR 68
__global__ __launch_bounds__(128) void attn_tf32_kernel()
{
    extern __shared__ float sm[];
    float* Ks = sm;
    float* Vs = sm + 64*ASTR;
    float* QP = sm + 2*64*ASTR;

    int qt = blockIdx.x, h = blockIdx.y;
    int kvh = h >> 2;
    int tid = threadIdx.x, warp = tid >> 5, lane = tid & 31;
    int g = lane >> 2, tg = lane & 3;
    int wq = warp * 16;
    int q0 = qt * 64;

    for (int i = tid; i < 64*16; i += 128) {
        int row = i >> 4, c4 = (i & 15) * 4;
        float4 v = *(const float4*)(g_q + ((size_t)h*SEQ + q0 + row)*HDIM + c4);
        QP[row*ASTR + c4 + 0] = __uint_as_float(f2tf32(v.x * 0.125f));
        QP[row*ASTR + c4 + 1] = __uint_as_float(f2tf32(v.y * 0.125f));
        QP[row*ASTR + c4 + 2] = __uint_as_float(f2tf32(v.z * 0.125f));
        QP[row*ASTR + c4 + 3] = __uint_as_float(f2tf32(v.w * 0.125f));
    }
    __syncthreads();
    uint32_t aq[8][4];
    #pragma unroll
    for (int kk = 0; kk < 8; kk++) {
        aq[kk][0] = __float_as_uint(QP[(wq+g)*ASTR + kk*8 + tg]);
        aq[kk][1] = __float_as_uint(QP[(wq+g+8)*ASTR + kk*8 + tg]);
        aq[kk][2] = __float_as_uint(QP[(wq+g)*ASTR + kk*8 + tg + 4]);
        aq[kk][3] = __float_as_uint(QP[(wq+g+8)*ASTR + kk*8 + tg + 4]);
    }
    __syncthreads();

    float oc[8][4];
    #pragma unroll
    for (int j = 0; j < 8; j++)
        #pragma unroll
        for (int q = 0; q < 4; q++) oc[j][q] = 0.f;
    float mrow[2] = {-1e30f, -1e30f};
    float lrow[2] = {0.f, 0.f};

    for (int kt = 0; kt <= qt; kt++) {
        for (int i = tid; i < 64*16; i += 128) {
            int row = i >> 4, c4 = (i & 15) * 4;
            size_t base = ((size_t)kvh*SEQ + kt*64 + row)*HDIM + c4;
            float4 kv = *(const float4*)(g_k + base);
            float4 vv = *(const float4*)(g_v + base);
            Ks[row*ASTR + c4 + 0] = __uint_as_float(f2tf32(kv.x));
            Ks[row*ASTR + c4 + 1] = __uint_as_float(f2tf32(kv.y));
            Ks[row*ASTR + c4 + 2] = __uint_as_float(f2tf32(kv.z));
            Ks[row*ASTR + c4 + 3] = __uint_as_float(f2tf32(kv.w));
            Vs[row*ASTR + c4 + 0] = __uint_as_float(f2tf32(vv.x));
            Vs[row*ASTR + c4 + 1] = __uint_as_float(f2tf32(vv.y));
            Vs[row*ASTR + c4 + 2] = __uint_as_float(f2tf32(vv.z));
            Vs[row*ASTR + c4 + 3] = __uint_as_float(f2tf32(vv.w));
        }
        __syncthreads();

        float sc[8][4];
        #pragma unroll
        for (int j = 0; j < 8; j++)
            #pragma unroll
            for (int q = 0; q < 4; q++) sc[j][q] = 0.f;
        #pragma unroll
        for (int kk = 0; kk < 8; kk++) {
            #pragma unroll
            for (int j = 0; j < 8; j++) {
                uint32_t b0 = __float_as_uint(Ks[(j*8+g)*ASTR + kk*8 + tg]);
                uint32_t b1 = __float_as_uint(Ks[(j*8+g)*ASTR + kk*8 + tg + 4]);
                mma_tf32(sc[j], aq[kk][0], aq[kk][1], aq[kk][2], aq[kk][3], b0, b1);
            }
        }

        if (kt == qt) {
            int r0g = q0 + wq + g, r1g = r0g + 8;
            #pragma unroll
            for (int j = 0; j < 8; j++) {
                int c0 = kt*64 + j*8 + tg*2;
                if (c0     > r0g) sc[j][0] = -1e30f;
                if (c0 + 1 > r0g) sc[j][1] = -1e30f;
                if (c0     > r1g) sc[j][2] = -1e30f;
                if (c0 + 1 > r1g) sc[j][3] = -1e30f;
            }
        }

        float mx0 = -1e30f, mx1 = -1e30f;
        #pragma unroll
        for (int j = 0; j < 8; j++) {
            mx0 = fmaxf(mx0, fmaxf(sc[j][0], sc[j][1]));
            mx1 = fmaxf(mx1, fmaxf(sc[j][2], sc[j][3]));
        }
        mx0 = fmaxf(mx0, __shfl_xor_sync(0xffffffffu, mx0, 1));
        mx0 = fmaxf(mx0, __shfl_xor_sync(0xffffffffu, mx0, 2));
        mx1 = fmaxf(mx1, __shfl_xor_sync(0xffffffffu, mx1, 1));
        mx1 = fmaxf(mx1, __shfl_xor_sync(0xffffffffu, mx1, 2));
        float mn0 = fmaxf(mrow[0], mx0), mn1 = fmaxf(mrow[1], mx1);
        float s0 = __expf(mrow[0] - mn0), s1 = __expf(mrow[1] - mn1);
        float ls0 = 0.f, ls1 = 0.f;
        #pragma unroll
        for (int j = 0; j < 8; j++) {
            sc[j][0] = __expf(sc[j][0] - mn0);
            sc[j][1] = __expf(sc[j][1] - mn0);
            sc[j][2] = __expf(sc[j][2] - mn1);
            sc[j][3] = __expf(sc[j][3] - mn1);
            ls0 += sc[j][0] + sc[j][1];
            ls1 += sc[j][2] + sc[j][3];
        }
        ls0 += __shfl_xor_sync(0xffffffffu, ls0, 1);
        ls0 += __shfl_xor_sync(0xffffffffu, ls0, 2);
        ls1 += __shfl_xor_sync(0xffffffffu, ls1, 1);
        ls1 += __shfl_xor_sync(0xffffffffu, ls1, 2);
        lrow[0] = lrow[0]*s0 + ls0;
        lrow[1] = lrow[1]*s1 + ls1;
        mrow[0] = mn0; mrow[1] = mn1;
        #pragma unroll
        for (int j = 0; j < 8; j++) {
            oc[j][0] *= s0; oc[j][1] *= s0;
            oc[j][2] *= s1; oc[j][3] *= s1;
        }

        #pragma unroll
        for (int j = 0; j < 8; j++) {
            float2 p0, p1;
            p0.x = __uint_as_float(f2tf32(sc[j][0]));
            p0.y = __uint_as_float(f2tf32(sc[j][1]));
            p1.x = __uint_as_float(f2tf32(sc[j][2]));
            p1.y = __uint_as_float(f2tf32(sc[j][3]));
            *(float2*)&QP[(wq+g)*ASTR + j*8 + tg*2]   = p0;
            *(float2*)&QP[(wq+g+8)*ASTR + j*8 + tg*2] = p1;
        }
        __syncwarp();

        #pragma unroll
        for (int kk = 0; kk < 8; kk++) {
            uint32_t a0 = __float_as_uint(QP[(wq+g)*ASTR + kk*8 + tg]);
            uint32_t a1 = __float_as_uint(QP[(wq+g+8)*ASTR + kk*8 + tg]);
            uint32_t a2 = __float_as_uint(QP[(wq+g)*ASTR + kk*8 + tg + 4]);
            uint32_t a3 = __float_as_uint(QP[(wq+g+8)*ASTR + kk*8 + tg + 4]);
            #pragma unroll
            for (int j = 0; j < 8; j++) {
                uint32_t b0 = __float_as_uint(Vs[(kk*8+tg)*ASTR + j*8 + g]);
                uint32_t b1 = __float_as_uint(Vs[(kk*8+tg+4)*ASTR + j*8 + g]);
                mma_tf32(oc[j], a0, a1, a2, a3, b0, b1);
            }
        }
        __syncthreads();
    }

    float inv0 = 1.f / lrow[0], inv1 = 1.f / lrow[1];
    #pragma unroll
    for (int j = 0; j < 8; j++) {
        int col = h*HDIM + j*8 + tg*2;
        __nv_bfloat162 b0 = __floats2bfloat162_rn(oc[j][0]*inv0, oc[j][1]*inv0);
        __nv_bfloat162 b1 = __floats2bfloat162_rn(oc[j][2]*inv1, oc[j][3]*inv1);
        *(__nv_bfloat162*)(g_y_bf + (size_t)(q0+wq+g)*DM + col)   = b0;
        *(__nv_bfloat162*)(g_y_bf + (size_t)(q0+wq+g+8)*DM + col) = b1;
    }
}

// ---------------- gating ----------------------------------------------------
__global__ __launch_bounds__(256) void gating_kernel(const float* __restrict__ gw)
{
    int t = blockIdx.x;
    int tid = threadIdx.x;
    int e = tid >> 5, lane = tid & 31;
    float s = 0.f;
    const float* hr = g_hf + (size_t)t*DM;
    const float* wr = gw + (size_t)e*DM;
    for (int d = lane; d < DM; d += 32) s += hr[d]*wr[d];
    #pragma unroll
    for (int ofs = 16; ofs > 0; ofs >>= 1) s += __shfl_down_sync(0xffffffffu, s, ofs);
    __shared__ float lg[NE];
    if (lane == 0) lg[e] = s;
    __syncthreads();
    if (tid == 0) {
        float mx = lg[0];
        #pragma unroll
        for (int i = 1; i < NE; i++) mx = fmaxf(mx, lg[i]);
        float p[NE]; float den = 0.f;
        #pragma unroll
        for (int i = 0; i < NE; i++) { p[i] = expf(lg[i]-mx); den += p[i]; }
        #pragma unroll
        for (int i = 0; i < NE; i++) p[i] /= den;
        int i1 = 0;
        #pragma unroll
        for (int i = 1; i < NE; i++) if (p[i] > p[i1]) i1 = i;
        int i2 = (i1 == 0) ? 1 : 0;
        #pragma unroll
        for (int i = 0; i < NE; i++) if (i != i1 && p[i] > p[i2]) i2 = i;
        float w1 = p[i1], w2 = p[i2];
        float sw2 = w1 + w2;
        w1 /= sw2; w2 /= sw2;
        int pos1 = atomicAdd(&g_cnt[i1], 1);
        g_slot[i1*SEQ + pos1] = 2*t;
        g_wslot[2*t] = w1;
        int pos2 = atomicAdd(&g_cnt[i2], 1);
        g_slot[i2*SEQ + pos2] = 2*t + 1;
        g_wslot[2*t+1] = w2;
    }
}

// ---------------- final combine ---------------------------------------------
__global__ __launch_bounds__(256) void combine_kernel(float* __restrict__ out)
{
    int t = blockIdx.x;
    int tid = threadIdx.x;
    float w0 = g_wslot[2*t], w1 = g_wslot[2*t+1];
    float4 hv = ((const float4*)(g_h + (size_t)t*DM))[tid];
    float4 a = ((const float4*)(g_os + (size_t)(2*t)*DM))[tid];
    float4 b = ((const float4*)(g_os + (size_t)(2*t+1)*DM))[tid];
    float4 o;
    o.x = hv.x + w0*a.x + w1*b.x;
    o.y = hv.y + w0*a.y + w1*b.y;
    o.z = hv.z + w0*a.z + w1*b.z;
    o.w = hv.w + w0*a.w + w1*b.w;
    ((float4*)(out + (size_t)t*DM))[tid] = o;
}

// ---------------- host launch ----------------------------------------------
#define GEMM_SMEM (6*GSTG)
#define W13_SMEM  (9*GSTG)
#define ATTN_SMEM (3*64*ASTR*(int)sizeof(float))

extern "C" void kernel_launch(void* const* d_in, const int* in_sizes, int n_in,
                              void* d_out, int out_size)
{
    const float* x      = (const float*)d_in[0];
    const float* wqkv   = (const float*)d_in[1];
    const float* wo     = (const float*)d_in[2];
    const float* gate_w = (const float*)d_in[3];
    const float* w1     = (const float*)d_in[4];
    const float* w2     = (const float*)d_in[5];
    const float* w3     = (const float*)d_in[6];
    const float* anw    = (const float*)d_in[7];
    const float* fnw    = (const float*)d_in[8];
    const float* freqs  = (const float*)d_in[9];
    float* out = (float*)d_out;

    bf16 *p_wqkv_bf, *p_wo_bf, *p_w1_bf, *p_w3_bf, *p_w2_bf;
    bf16 *p_hn_bf, *p_hf_bf, *p_y_bf, *p_gb;
    float *p_qkv, *p_h, *p_hf, *p_os;
    int *p_cnt;
    cudaGetSymbolAddress((void**)&p_wqkv_bf, g_wqkv_bf);
    cudaGetSymbolAddress((void**)&p_wo_bf,   g_wo_bf);
    cudaGetSymbolAddress((void**)&p_w1_bf,   g_w1_bf);
    cudaGetSymbolAddress((void**)&p_w3_bf,   g_w3_bf);
    cudaGetSymbolAddress((void**)&p_w2_bf,   g_w2_bf);
    cudaGetSymbolAddress((void**)&p_hn_bf,   g_hn_bf);
    cudaGetSymbolAddress((void**)&p_hf_bf,   g_hf_bf);
    cudaGetSymbolAddress((void**)&p_y_bf,    g_y_bf);
    cudaGetSymbolAddress((void**)&p_gb,      g_gb);
    cudaGetSymbolAddress((void**)&p_qkv,     g_qkv);
    cudaGetSymbolAddress((void**)&p_h,       g_h);
    cudaGetSymbolAddress((void**)&p_hf,      g_hf);
    cudaGetSymbolAddress((void**)&p_os,      g_os);
    cudaGetSymbolAddress((void**)&p_cnt,     g_cnt);

    static bool attr_set = false;
    if (!attr_set) {
        cudaFuncSetAttribute(attn_tf32_kernel,
            cudaFuncAttributeMaxDynamicSharedMemorySize, ATTN_SMEM);
        cudaFuncSetAttribute(gemm_bf<false>,
            cudaFuncAttributeMaxDynamicSharedMemorySize, GEMM_SMEM);
        cudaFuncSetAttribute(gemm_bf<true>,
            cudaFuncAttributeMaxDynamicSharedMemorySize, GEMM_SMEM);
        cudaFuncSetAttribute(gemm_w13,
            cudaFuncAttributeMaxDynamicSharedMemorySize, W13_SMEM);
        attr_set = true;
    }

    // 0. convert weights fp32 -> bf16
    {
        int n4;
        n4 = QKVN*DM/4;
        f2bf_kernel<<<(n4+255)/256, 256>>>((const float4*)wqkv, (uint2*)p_wqkv_bf, n4);
        n4 = DM*DM/4;
        f2bf_kernel<<<(n4+255)/256, 256>>>((const float4*)wo, (uint2*)p_wo_bf, n4);
        n4 = (int)((size_t)NE*NI*DM/4);
        f2bf_kernel<<<(n4+255)/256, 256>>>((const float4*)w1, (uint2*)p_w1_bf, n4);
        f2bf_kernel<<<(n4+255)/256, 256>>>((const float4*)w3, (uint2*)p_w3_bf, n4);
        f2bf_kernel<<<(n4+255)/256, 256>>>((const float4*)w2, (uint2*)p_w2_bf, n4);
    }
    // 1. attn rmsnorm (bf16 only)
    rmsnorm_kernel<<<SEQ, 256>>>(x, anw, p_hn_bf, nullptr);
    // 2. qkv = hn @ wqkv^T (bf16 HMMA)
    gemm_bf<false><<<dim3(QKVN/128, SEQ/128), 256, GEMM_SMEM>>>(
        p_hn_bf, p_wqkv_bf, nullptr, p_qkv, SEQ, QKVN, DM, 0);
    // 3. rope + split
    {
        int total = SEQ * (QKVN/2);
        rope_split_kernel<<<(total + 255)/256, 256>>>(freqs);
    }
    // 4. attention (tf32)
    attn_tf32_kernel<<<dim3(SEQ/64, NH), 128, ATTN_SMEM>>>();
    // 5. h = x + y @ wo^T
    gemm_bf<false><<<dim3(DM/128, SEQ/128), 256, GEMM_SMEM>>>(
        p_y_bf, p_wo_bf, x, p_h, SEQ, DM, DM, 0);
    // 6. ffn rmsnorm (bf16 + fp32 for gating)
    rmsnorm_kernel<<<SEQ, 256>>>(p_h, fnw, p_hf_bf, p_hf);
    // 7. gating
    cudaMemsetAsync(p_cnt, 0, NE*sizeof(int), 0);
    gating_kernel<<<SEQ, 256>>>(gate_w);
    // 8. fused MoE w1/w3 + silu*mul -> g_gb (bf16)
    gemm_w13<<<dim3(NI/128, SEQ/128, NE), 256, W13_SMEM>>>(
        p_hf_bf, p_w1_bf, p_w3_bf);
    // 9. out_slot = g @ w2^T (bf16 HMMA, gathered)
    gemm_bf<true><<<dim3(DM/128, SEQ/128, NE), 256, GEMM_SMEM>>>(
        p_gb, p_w2_bf, nullptr, p_os, 0, DM, NI, 0);
    // 10. combine
    combine_kernel<<<SEQ, 256>>>(out);
}